// round 9
// baseline (speedup 1.0000x reference)
#include <cuda_runtime.h>
#include <cuda_fp16.h>
#include <cstdint>

// ---------------- problem constants ----------------
#define Dc   1024
#define Ec   8
#define Hc   2730
#define HP2  2816            // H padded to 22*128
#define NT   8192
#define TMp  128             // per-expert row padding
#define MMAX (2*NT + Ec*TMp) // 17408
#define KCH  64              // K halves per pipeline chunk (4 x k16)

// smem strides (halves)
#define SA1  72              // A row stride (64 K + 8 pad)  = 144 B
#define SBF1 72              // FFN1 B row stride (64 N + 8 pad)
#define SBF2 136             // FFN2 B row stride (128 N + 8 pad) = 272 B

// FFN1 stage (halves): A[128][72]=9216, B1[64][72]=4608, B3[64][72]=4608
#define F1_B1OFF 9216
#define F1_B3OFF 13824
#define F1_STGH  18432
#define F1_SMEM  (3 * F1_STGH * 2)    // 110592 B  (2 CTAs/SM)
// FFN2 stage: A[128][72]=9216, B[64][136]=8704
#define F2_BOFF  9216
#define F2_STGH  17920
#define F2_SMEM  (3 * F2_STGH * 2)    // 107520 B  (2 CTAs/SM)

// ---------------- device scratch ----------------
__device__ int    g_cnt[Ec];
__device__ int    g_cur[Ec];
__device__ int    g_off[Ec + 1];
__device__ int    g_tok[MMAX];
__device__ float  g_gate[MMAX];
__device__ int    g_topi[NT * 2];
__device__ float  g_topv[NT * 2];
__device__ int    g_pos[NT * 2];
__device__ __half g_w1h[(size_t)Ec * Dc * HP2];   // W1 fp16 [E][Dc][HP2]
__device__ __half g_w3h[(size_t)Ec * Dc * HP2];   // W3 fp16
__device__ __half g_w2h[(size_t)Ec * HP2 * Dc];   // W2 fp16 [E][HP2][Dc]
__device__ __half g_xh[(size_t)NT * Dc];          // x fp16
__device__ __half g_h[(size_t)MMAX * HP2];        // activations fp16
__device__ float  g_y[(size_t)MMAX * Dc];

// ---------------- helpers ----------------
__device__ __forceinline__ uint32_t smem_u32(const void* p) {
    uint32_t a;
    asm("{ .reg .u64 t; cvta.to.shared.u64 t, %1; cvt.u32.u64 %0, t; }" : "=r"(a) : "l"(p));
    return a;
}
#define CP16(dst, src) asm volatile("cp.async.cg.shared.global [%0], [%1], 16;" :: "r"(dst), "l"(src) : "memory")
#define CP_COMMIT()    asm volatile("cp.async.commit_group;" ::: "memory")
#define CP_WAIT0()     asm volatile("cp.async.wait_group 0;" ::: "memory")
#define CP_WAIT1()     asm volatile("cp.async.wait_group 1;" ::: "memory")

__device__ __forceinline__ void ldsm_x4(uint32_t* r, uint32_t a) {
    asm volatile("ldmatrix.sync.aligned.m8n8.x4.shared.b16 {%0,%1,%2,%3}, [%4];"
        : "=r"(r[0]), "=r"(r[1]), "=r"(r[2]), "=r"(r[3]) : "r"(a));
}
__device__ __forceinline__ void ldsm_x4t(uint32_t* r, uint32_t a) {
    asm volatile("ldmatrix.sync.aligned.m8n8.x4.trans.shared.b16 {%0,%1,%2,%3}, [%4];"
        : "=r"(r[0]), "=r"(r[1]), "=r"(r[2]), "=r"(r[3]) : "r"(a));
}
__device__ __forceinline__ void mma16(float* d, const uint32_t* a, const uint32_t* b) {
    asm volatile(
        "mma.sync.aligned.m16n8k16.row.col.f32.f16.f16.f32 "
        "{%0,%1,%2,%3}, {%4,%5,%6,%7}, {%8,%9}, {%0,%1,%2,%3};"
        : "+f"(d[0]), "+f"(d[1]), "+f"(d[2]), "+f"(d[3])
        : "r"(a[0]), "r"(a[1]), "r"(a[2]), "r"(a[3]), "r"(b[0]), "r"(b[1]));
}

// ---------------- launch 1: convert W1,W3 to fp16 (+zero bookkeeping) ----------------
__global__ void k_prep(const float* __restrict__ W1, const float* __restrict__ W3) {
    int gid = blockIdx.x * blockDim.x + threadIdx.x;
    if (gid < Ec) { g_cnt[gid] = 0; g_cur[gid] = 0; }
    if (gid < MMAX) { g_tok[gid] = -1; g_gate[gid] = 0.0f; }

    int row = blockIdx.x;                       // 0 .. E*Dc-1
    const float* i1 = W1 + (size_t)row * Hc;
    const float* i3 = W3 + (size_t)row * Hc;
    __half* o1 = g_w1h + (size_t)row * HP2;
    __half* o3 = g_w3h + (size_t)row * HP2;
    for (int u = threadIdx.x; u < HP2 / 8; u += 256) {
        int j = u * 8;
        __half2 v1[4], v3[4];
        if (j + 8 <= Hc) {
            float2 a0 = *(const float2*)(i1 + j),     a1 = *(const float2*)(i1 + j + 2);
            float2 a2 = *(const float2*)(i1 + j + 4), a3 = *(const float2*)(i1 + j + 6);
            v1[0] = __floats2half2_rn(a0.x, a0.y); v1[1] = __floats2half2_rn(a1.x, a1.y);
            v1[2] = __floats2half2_rn(a2.x, a2.y); v1[3] = __floats2half2_rn(a3.x, a3.y);
            float2 b0 = *(const float2*)(i3 + j),     b1 = *(const float2*)(i3 + j + 2);
            float2 b2 = *(const float2*)(i3 + j + 4), b3 = *(const float2*)(i3 + j + 6);
            v3[0] = __floats2half2_rn(b0.x, b0.y); v3[1] = __floats2half2_rn(b1.x, b1.y);
            v3[2] = __floats2half2_rn(b2.x, b2.y); v3[3] = __floats2half2_rn(b3.x, b3.y);
        } else {
#pragma unroll
            for (int t = 0; t < 4; t++) {
                int c0 = j + 2 * t, c1 = j + 2 * t + 1;
                float f0 = (c0 < Hc) ? i1[c0] : 0.f;
                float f1 = (c1 < Hc) ? i1[c1] : 0.f;
                v1[t] = __floats2half2_rn(f0, f1);
                float g0 = (c0 < Hc) ? i3[c0] : 0.f;
                float g1 = (c1 < Hc) ? i3[c1] : 0.f;
                v3[t] = __floats2half2_rn(g0, g1);
            }
        }
        *(uint4*)(o1 + j) = *(uint4*)v1;
        *(uint4*)(o3 + j) = *(uint4*)v3;
    }
}

// ---------------- launch 5: convert W2 to fp16 (row-padded) ----------------
__global__ void k_w2h(const float* __restrict__ in) {
    int row = blockIdx.x;                       // 0 .. E*HP2-1
    int e = row / HP2, hp = row % HP2;
    __half* op = g_w2h + (size_t)row * Dc;
    int j = threadIdx.x * 8;                    // 128 threads * 8 = 1024
    __half2 v[4];
    if (hp < Hc) {
        const float* ip = in + ((size_t)e * Hc + hp) * Dc + j;
        float4 a = *(const float4*)ip, b = *(const float4*)(ip + 4);
        v[0] = __floats2half2_rn(a.x, a.y); v[1] = __floats2half2_rn(a.z, a.w);
        v[2] = __floats2half2_rn(b.x, b.y); v[3] = __floats2half2_rn(b.z, b.w);
    } else {
        v[0] = v[1] = v[2] = v[3] = __floats2half2_rn(0.f, 0.f);
    }
    *(uint4*)(op + j) = *(uint4*)v;
}

// ---------------- launch 2: router (+ x -> fp16) ----------------
__global__ void k_routerx(const float* __restrict__ x, const float* __restrict__ Wr) {
    int warp = threadIdx.x >> 5, lane = threadIdx.x & 31;
    int n = blockIdx.x * 8 + warp;
    if (n >= NT) return;
    const float* xr = x + (size_t)n * Dc;
    __half* xo = g_xh + (size_t)n * Dc;
    float acc[Ec];
#pragma unroll
    for (int e = 0; e < Ec; e++) acc[e] = 0.0f;
    for (int d0 = lane * 4; d0 < Dc; d0 += 128) {
        float4 xv = *(const float4*)(xr + d0);
        __half2 h01 = __floats2half2_rn(xv.x, xv.y);
        __half2 h23 = __floats2half2_rn(xv.z, xv.w);
        uint2 pk;
        pk.x = *(uint32_t*)&h01; pk.y = *(uint32_t*)&h23;
        *(uint2*)(xo + d0) = pk;
        float xs[4] = {xv.x, xv.y, xv.z, xv.w};
#pragma unroll
        for (int j = 0; j < 4; j++) {
            float4 w0 = *(const float4*)(Wr + (d0 + j) * Ec);
            float4 w1 = *(const float4*)(Wr + (d0 + j) * Ec + 4);
            acc[0] += xs[j] * w0.x; acc[1] += xs[j] * w0.y;
            acc[2] += xs[j] * w0.z; acc[3] += xs[j] * w0.w;
            acc[4] += xs[j] * w1.x; acc[5] += xs[j] * w1.y;
            acc[6] += xs[j] * w1.z; acc[7] += xs[j] * w1.w;
        }
    }
#pragma unroll
    for (int e = 0; e < Ec; e++)
#pragma unroll
        for (int o = 16; o > 0; o >>= 1)
            acc[e] += __shfl_xor_sync(0xffffffffu, acc[e], o);
    if (lane == 0) {
        float mx = acc[0];
#pragma unroll
        for (int e = 1; e < Ec; e++) mx = fmaxf(mx, acc[e]);
        float p[Ec], s = 0.0f;
#pragma unroll
        for (int e = 0; e < Ec; e++) { p[e] = __expf(acc[e] - mx); s += p[e]; }
        float inv = 1.0f / s;
        int i1 = 0;
#pragma unroll
        for (int e = 1; e < Ec; e++) if (p[e] > p[i1]) i1 = e;
        int i2 = (i1 == 0) ? 1 : 0;
#pragma unroll
        for (int e = 0; e < Ec; e++) if (e != i1 && p[e] > p[i2]) i2 = e;
        g_topi[2 * n] = i1;     g_topv[2 * n] = p[i1] * inv;
        g_topi[2 * n + 1] = i2; g_topv[2 * n + 1] = p[i2] * inv;
        atomicAdd(&g_cnt[i1], 1);
        atomicAdd(&g_cnt[i2], 1);
    }
}

// ---------------- launch 3: fused scan + scatter ----------------
__global__ void k_scansc() {
    __shared__ int soff[Ec];
    if (threadIdx.x == 0) {
        int o = 0;
#pragma unroll
        for (int e = 0; e < Ec; e++) {
            soff[e] = o;
            o += ((g_cnt[e] + TMp - 1) / TMp) * TMp;
        }
        if (blockIdx.x == 0) {
#pragma unroll
            for (int e = 0; e < Ec; e++) g_off[e] = soff[e];
            g_off[Ec] = o;
        }
    }
    __syncthreads();
    int n = blockIdx.x * blockDim.x + threadIdx.x;
    if (n >= NT) return;
#pragma unroll
    for (int k = 0; k < 2; k++) {
        int e = g_topi[2 * n + k];
        int pos = soff[e] + atomicAdd(&g_cur[e], 1);
        g_tok[pos] = n;
        g_gate[pos] = g_topv[2 * n + k];
        g_pos[2 * n + k] = pos;
    }
}

// ============ launch 4: FFN1  h = silu(X@W1) * (X@W3)
// CTA 128x64, 128 threads, 4 warps (2x2), warp tile 64x32 per GEMM, 2 CTA/SM
__global__ void __launch_bounds__(128, 2) k_ffn1() {
    extern __shared__ __half sm[];
    int m0 = blockIdx.y * 128;
    if (m0 >= g_off[Ec]) return;
    int e = 0;
#pragma unroll
    for (int i = 1; i < Ec; i++) if (m0 >= g_off[i]) e = i;
    int n0 = blockIdx.x * 64;

    int tid = threadIdx.x, wid = tid >> 5, lane = tid & 31;
    int wm = wid & 1, wn = wid >> 1;              // 2x2 warp grid
    int gi = lane >> 2, ti = lane & 3;
    uint32_t smb = smem_u32(sm);

    // loaders: A 128 rows x 64 halves (1 thr/row, 8 CP16); B 64x64 (2 thr/row, 4 CP16 each)
    int rA = tid;
    int rB = tid >> 1, cB = (tid & 1) * 32;
    int tok = g_tok[m0 + rA];
    const __half* srcA  = g_xh + (size_t)(tok < 0 ? 0 : tok) * Dc;
    const __half* srcB1 = g_w1h + ((size_t)e * Dc + rB) * HP2 + n0 + cB;
    const __half* srcB3 = g_w3h + ((size_t)e * Dc + rB) * HP2 + n0 + cB;
    uint32_t dstA  = smb + (uint32_t)(rA * SA1) * 2;
    uint32_t dstB1 = smb + (uint32_t)(F1_B1OFF + rB * SBF1 + cB) * 2;
    uint32_t dstB3 = smb + (uint32_t)(F1_B3OFF + rB * SBF1 + cB) * 2;
    const uint32_t STGB = (uint32_t)F1_STGH * 2;

    auto issue = [&](int kc, int buf) {
        int k0 = kc * KCH;
        uint32_t so = buf * STGB;
        const __half* sA = srcA + k0;
        uint32_t dA = dstA + so;
#pragma unroll
        for (int q = 0; q < 8; q++) CP16(dA + q * 16, sA + q * 8);
        const __half* s1 = srcB1 + (size_t)k0 * HP2;
        uint32_t d1 = dstB1 + so;
#pragma unroll
        for (int q = 0; q < 4; q++) CP16(d1 + q * 16, s1 + q * 8);
        const __half* s3 = srcB3 + (size_t)k0 * HP2;
        uint32_t d3 = dstB3 + so;
#pragma unroll
        for (int q = 0; q < 4; q++) CP16(d3 + q * 16, s3 + q * 8);
    };

    // fragment bases
    int aRow = wm * 64 + (lane & 7) + 8 * ((lane >> 3) & 1);
    uint32_t aBase = smb + (uint32_t)(aRow * SA1 + 8 * (lane >> 4)) * 2;
    int bRowK = (lane & 7) + 8 * ((lane >> 3) & 1);
    uint32_t bBase = smb + (uint32_t)(F1_B1OFF + bRowK * SBF1 + wn * 32 + (lane >> 4) * 8) * 2;
    const uint32_t B3D = (uint32_t)(F1_B3OFF - F1_B1OFF) * 2;   // 9216

    float acc1[4][4][4], acc3[4][4][4];
#pragma unroll
    for (int mt = 0; mt < 4; mt++)
#pragma unroll
        for (int nt = 0; nt < 4; nt++)
#pragma unroll
            for (int j = 0; j < 4; j++) { acc1[mt][nt][j] = 0.f; acc3[mt][nt][j] = 0.f; }

    const int nc = Dc / KCH;   // 16
    issue(0, 0); CP_COMMIT();
    issue(1, 1); CP_COMMIT();

    for (int c = 0; c < nc; ++c) {
        if (c + 1 < nc) CP_WAIT1(); else CP_WAIT0();
        __syncthreads();
        if (c + 2 < nc) { issue(c + 2, (c + 2) % 3); CP_COMMIT(); }
        uint32_t so = (uint32_t)(c % 3) * STGB;
        uint32_t aA = aBase + so;
        uint32_t bB = bBase + so;
#pragma unroll
        for (int ks = 0; ks < 4; ks++) {
            uint32_t af[4][4];
#pragma unroll
            for (int mt = 0; mt < 4; mt++)
                ldsm_x4(af[mt], aA + ks * 32 + mt * 2304);   // +16 rows * 144B per mt
#pragma unroll
            for (int np = 0; np < 2; np++) {
                uint32_t bo = bB + ks * 2304 + np * 32;       // +16 k-rows * 144B ; +16 cols
                uint32_t bf1[4], bf3[4];
                ldsm_x4t(bf1, bo);
                ldsm_x4t(bf3, bo + B3D);
#pragma unroll
                for (int mt = 0; mt < 4; mt++) {
                    mma16(acc1[mt][2 * np],     af[mt], bf1);
                    mma16(acc1[mt][2 * np + 1], af[mt], bf1 + 2);
                    mma16(acc3[mt][2 * np],     af[mt], bf3);
                    mma16(acc3[mt][2 * np + 1], af[mt], bf3 + 2);
                }
            }
        }
    }

    // epilogue: silu(d1)*d3 -> g_h (fp16)
#pragma unroll
    for (int mt = 0; mt < 4; mt++) {
#pragma unroll
        for (int nt = 0; nt < 4; nt++) {
            int row = m0 + wm * 64 + mt * 16 + gi;
            int col = n0 + wn * 32 + nt * 8 + 2 * ti;
            const float* d1 = acc1[mt][nt];
            const float* d3 = acc3[mt][nt];
            float h0 = d1[0] / (1.0f + __expf(-d1[0])) * d3[0];
            float h1 = d1[1] / (1.0f + __expf(-d1[1])) * d3[1];
            float h2 = d1[2] / (1.0f + __expf(-d1[2])) * d3[2];
            float h3 = d1[3] / (1.0f + __expf(-d1[3])) * d3[3];
            *(__half2*)(g_h + (size_t)row * HP2 + col)       = __floats2half2_rn(h0, h1);
            *(__half2*)(g_h + (size_t)(row + 8) * HP2 + col) = __floats2half2_rn(h2, h3);
        }
    }
}

// ============ launch 6: FFN2  y = gate * (h @ W2)
// CTA 128x128, 128 threads, 4 warps (2x2), warp tile 64x64, 2 CTA/SM
__global__ void __launch_bounds__(128, 2) k_ffn2() {
    extern __shared__ __half sm[];
    int m0 = blockIdx.y * 128;
    if (m0 >= g_off[Ec]) return;
    int e = 0;
#pragma unroll
    for (int i = 1; i < Ec; i++) if (m0 >= g_off[i]) e = i;
    int n0 = blockIdx.x * 128;

    int tid = threadIdx.x, wid = tid >> 5, lane = tid & 31;
    int wm = wid & 1, wn = wid >> 1;              // 2x2 warp grid
    int gi = lane >> 2, ti = lane & 3;
    uint32_t smb = smem_u32(sm);

    int rA = tid;                                  // A: 128 rows, 8 CP16/thread
    int rB = tid >> 1, cB = (tid & 1) * 64;        // B: 64 rows x 128 halves, 8 CP16/thread
    const __half* srcA = g_h + (size_t)(m0 + rA) * HP2;
    const __half* srcB = g_w2h + ((size_t)e * HP2 + rB) * Dc + n0 + cB;
    uint32_t dstA = smb + (uint32_t)(rA * SA1) * 2;
    uint32_t dstB = smb + (uint32_t)(F2_BOFF + rB * SBF2 + cB) * 2;
    const uint32_t STGB = (uint32_t)F2_STGH * 2;

    auto issue = [&](int kc, int buf) {
        int k0 = kc * KCH;
        uint32_t so = buf * STGB;
        const __half* sA = srcA + k0;
        uint32_t dA = dstA + so;
#pragma unroll
        for (int q = 0; q < 8; q++) CP16(dA + q * 16, sA + q * 8);
        const __half* sB = srcB + (size_t)k0 * Dc;
        uint32_t dB = dstB + so;
#pragma unroll
        for (int q = 0; q < 8; q++) CP16(dB + q * 16, sB + q * 8);
    };

    int aRow = wm * 64 + (lane & 7) + 8 * ((lane >> 3) & 1);
    uint32_t aBase = smb + (uint32_t)(aRow * SA1 + 8 * (lane >> 4)) * 2;
    int bRowK = (lane & 7) + 8 * ((lane >> 3) & 1);
    uint32_t bBase = smb + (uint32_t)(F2_BOFF + bRowK * SBF2 + wn * 64 + (lane >> 4) * 8) * 2;

    float acc[4][8][4];
#pragma unroll
    for (int mt = 0; mt < 4; mt++)
#pragma unroll
        for (int nt = 0; nt < 8; nt++)
#pragma unroll
            for (int j = 0; j < 4; j++) acc[mt][nt][j] = 0.f;

    const int nc = HP2 / KCH;   // 44
    issue(0, 0); CP_COMMIT();
    issue(1, 1); CP_COMMIT();

    for (int c = 0; c < nc; ++c) {
        if (c + 1 < nc) CP_WAIT1(); else CP_WAIT0();
        __syncthreads();
        if (c + 2 < nc) { issue(c + 2, (c + 2) % 3); CP_COMMIT(); }
        uint32_t so = (uint32_t)(c % 3) * STGB;
        uint32_t aA = aBase + so;
        uint32_t bB = bBase + so;
#pragma unroll
        for (int ks = 0; ks < 4; ks++) {
            uint32_t af[4][4];
#pragma unroll
            for (int mt = 0; mt < 4; mt++)
                ldsm_x4(af[mt], aA + ks * 32 + mt * 2304);
#pragma unroll
            for (int np = 0; np < 4; np++) {
                uint32_t bf[4];
                ldsm_x4t(bf, bB + ks * 4352 + np * 32);      // +16 k-rows * 272B ; +16 cols
#pragma unroll
                for (int mt = 0; mt < 4; mt++) {
                    mma16(acc[mt][2 * np],     af[mt], bf);
                    mma16(acc[mt][2 * np + 1], af[mt], bf + 2);
                }
            }
        }
    }

    // epilogue: gate multiply -> g_y (fp32)
#pragma unroll
    for (int mt = 0; mt < 4; mt++) {
        int row = m0 + wm * 64 + mt * 16 + gi;
        float ga = g_gate[row];
        float gb = g_gate[row + 8];
#pragma unroll
        for (int nt = 0; nt < 8; nt++) {
            int col = n0 + wn * 64 + nt * 8 + 2 * ti;
            const float* d = acc[mt][nt];
            float2 o0, o1;
            o0.x = ga * d[0]; o0.y = ga * d[1];
            o1.x = gb * d[2]; o1.y = gb * d[3];
            *(float2*)(g_y + (size_t)row * Dc + col) = o0;
            *(float2*)(g_y + (size_t)(row + 8) * Dc + col) = o1;
        }
    }
}

// ---------------- launch 7: combine ----------------
__global__ void k_combine(float* __restrict__ out) {
    int i = blockIdx.x * blockDim.x + threadIdx.x;
    int n = i >> 8;
    int c = (i & 255) * 4;
    int p0 = g_pos[2 * n], p1 = g_pos[2 * n + 1];
    float4 a = *(const float4*)&g_y[(size_t)p0 * Dc + c];
    float4 b = *(const float4*)&g_y[(size_t)p1 * Dc + c];
    float4 o;
    o.x = a.x + b.x; o.y = a.y + b.y; o.z = a.z + b.z; o.w = a.w + b.w;
    *(float4*)(out + (size_t)n * Dc + c) = o;
}

// ---------------- launch ----------------
extern "C" void kernel_launch(void* const* d_in, const int* in_sizes, int n_in,
                              void* d_out, int out_size) {
    const float* x  = (const float*)d_in[0];
    const float* Wr = (const float*)d_in[1];
    const float* W1 = (const float*)d_in[2];
    const float* W2 = (const float*)d_in[3];
    const float* W3 = (const float*)d_in[4];
    float* out = (float*)d_out;

    cudaFuncSetAttribute(k_ffn1, cudaFuncAttributeMaxDynamicSharedMemorySize, F1_SMEM);
    cudaFuncSetAttribute(k_ffn2, cudaFuncAttributeMaxDynamicSharedMemorySize, F2_SMEM);

    k_prep<<<Ec * Dc, 256>>>(W1, W3);                        // 1
    k_routerx<<<NT / 8, 256>>>(x, Wr);                       // 2
    k_scansc<<<NT / 256, 256>>>();                           // 3
    k_ffn1<<<dim3(HP2 / 64, MMAX / 128), 128, F1_SMEM>>>();  // 4  <- profiled
    k_w2h<<<Ec * HP2, 128>>>(W2);                            // 5
    k_ffn2<<<dim3(Dc / 128, MMAX / 128), 128, F2_SMEM>>>();  // 6
    k_combine<<<(NT * (Dc / 4)) / 256, 256>>>(out);          // 7
}

// round 10
// speedup vs baseline: 1.2186x; 1.2186x over previous
#include <cuda_runtime.h>
#include <cuda_fp16.h>
#include <cstdint>

// ---------------- problem constants ----------------
#define Dc   1024
#define Ec   8
#define Hc   2730
#define HP2  2816            // H padded to 22*128
#define NT   8192
#define TMp  128             // per-expert row padding
#define MMAX (2*NT + Ec*TMp) // 17408
#define KCH  64              // K halves per pipeline chunk (4 x k16)

// smem strides (halves)
#define SA1  72              // A row stride (64 K + 8 pad)  = 144 B
#define SBF1 72              // FFN1 B row stride (64 N + 8 pad)
#define SBF2 136             // FFN2 B row stride (128 N + 8 pad) = 272 B

// FFN1 stage (halves): A[128][72]=9216, B1[64][72]=4608, B3[64][72]=4608
#define F1_B1OFF 9216
#define F1_B3OFF 13824
#define F1_STGH  18432
#define F1_SMEM  (3 * F1_STGH * 2)    // 110592 B  (2 CTAs/SM)
// FFN2 stage: A[128][72]=9216, B[64][136]=8704
#define F2_BOFF  9216
#define F2_STGH  17920
#define F2_SMEM  (3 * F2_STGH * 2)    // 107520 B  (2 CTAs/SM)

// conversion-role rows prepended to k_ffn1's grid.y
#define W2Y  256              // 256 y-rows * 44 x = 11264 blocks, 2 W2-rows each

// ---------------- device scratch ----------------
__device__ int    g_cnt[Ec];
__device__ int    g_cur[Ec];
__device__ int    g_off[Ec + 1];
__device__ int    g_tok[MMAX];
__device__ float  g_gate[MMAX];
__device__ int    g_topi[NT * 2];
__device__ float  g_topv[NT * 2];
__device__ int    g_pos[NT * 2];
__device__ __half g_w1h[(size_t)Ec * Dc * HP2];   // W1 fp16 [E][Dc][HP2]
__device__ __half g_w3h[(size_t)Ec * Dc * HP2];   // W3 fp16
__device__ __half g_w2h[(size_t)Ec * HP2 * Dc];   // W2 fp16 [E][HP2][Dc]
__device__ __half g_xh[(size_t)NT * Dc];          // x fp16
__device__ __half g_h[(size_t)MMAX * HP2];        // activations fp16
__device__ float  g_y[(size_t)MMAX * Dc];

// ---------------- helpers ----------------
__device__ __forceinline__ uint32_t smem_u32(const void* p) {
    uint32_t a;
    asm("{ .reg .u64 t; cvta.to.shared.u64 t, %1; cvt.u32.u64 %0, t; }" : "=r"(a) : "l"(p));
    return a;
}
#define CP16(dst, src) asm volatile("cp.async.cg.shared.global [%0], [%1], 16;" :: "r"(dst), "l"(src) : "memory")
#define CP_COMMIT()    asm volatile("cp.async.commit_group;" ::: "memory")
#define CP_WAIT0()     asm volatile("cp.async.wait_group 0;" ::: "memory")
#define CP_WAIT1()     asm volatile("cp.async.wait_group 1;" ::: "memory")

__device__ __forceinline__ void ldsm_x4(uint32_t* r, uint32_t a) {
    asm volatile("ldmatrix.sync.aligned.m8n8.x4.shared.b16 {%0,%1,%2,%3}, [%4];"
        : "=r"(r[0]), "=r"(r[1]), "=r"(r[2]), "=r"(r[3]) : "r"(a));
}
__device__ __forceinline__ void ldsm_x4t(uint32_t* r, uint32_t a) {
    asm volatile("ldmatrix.sync.aligned.m8n8.x4.trans.shared.b16 {%0,%1,%2,%3}, [%4];"
        : "=r"(r[0]), "=r"(r[1]), "=r"(r[2]), "=r"(r[3]) : "r"(a));
}
__device__ __forceinline__ void mma16(float* d, const uint32_t* a, const uint32_t* b) {
    asm volatile(
        "mma.sync.aligned.m16n8k16.row.col.f32.f16.f16.f32 "
        "{%0,%1,%2,%3}, {%4,%5,%6,%7}, {%8,%9}, {%0,%1,%2,%3};"
        : "+f"(d[0]), "+f"(d[1]), "+f"(d[2]), "+f"(d[3])
        : "r"(a[0]), "r"(a[1]), "r"(a[2]), "r"(a[3]), "r"(b[0]), "r"(b[1]));
}

// ---------------- launch 1: convert W1,W3 to fp16 (+zero bookkeeping) ----------------
__global__ void k_prep(const float* __restrict__ W1, const float* __restrict__ W3) {
    int gid = blockIdx.x * blockDim.x + threadIdx.x;
    if (gid < Ec) { g_cnt[gid] = 0; g_cur[gid] = 0; }
    if (gid < MMAX) { g_tok[gid] = -1; g_gate[gid] = 0.0f; }

    int row = blockIdx.x;                       // 0 .. E*Dc-1
    const float* i1 = W1 + (size_t)row * Hc;
    const float* i3 = W3 + (size_t)row * Hc;
    __half* o1 = g_w1h + (size_t)row * HP2;
    __half* o3 = g_w3h + (size_t)row * HP2;
    for (int u = threadIdx.x; u < HP2 / 8; u += 256) {
        int j = u * 8;
        __half2 v1[4], v3[4];
        if (j + 8 <= Hc) {
            float2 a0 = *(const float2*)(i1 + j),     a1 = *(const float2*)(i1 + j + 2);
            float2 a2 = *(const float2*)(i1 + j + 4), a3 = *(const float2*)(i1 + j + 6);
            v1[0] = __floats2half2_rn(a0.x, a0.y); v1[1] = __floats2half2_rn(a1.x, a1.y);
            v1[2] = __floats2half2_rn(a2.x, a2.y); v1[3] = __floats2half2_rn(a3.x, a3.y);
            float2 b0 = *(const float2*)(i3 + j),     b1 = *(const float2*)(i3 + j + 2);
            float2 b2 = *(const float2*)(i3 + j + 4), b3 = *(const float2*)(i3 + j + 6);
            v3[0] = __floats2half2_rn(b0.x, b0.y); v3[1] = __floats2half2_rn(b1.x, b1.y);
            v3[2] = __floats2half2_rn(b2.x, b2.y); v3[3] = __floats2half2_rn(b3.x, b3.y);
        } else {
#pragma unroll
            for (int t = 0; t < 4; t++) {
                int c0 = j + 2 * t, c1 = j + 2 * t + 1;
                float f0 = (c0 < Hc) ? i1[c0] : 0.f;
                float f1 = (c1 < Hc) ? i1[c1] : 0.f;
                v1[t] = __floats2half2_rn(f0, f1);
                float g0 = (c0 < Hc) ? i3[c0] : 0.f;
                float g1 = (c1 < Hc) ? i3[c1] : 0.f;
                v3[t] = __floats2half2_rn(g0, g1);
            }
        }
        *(uint4*)(o1 + j) = *(uint4*)v1;
        *(uint4*)(o3 + j) = *(uint4*)v3;
    }
}

// ---------------- launch 2: router (+ x -> fp16) ----------------
__global__ void k_routerx(const float* __restrict__ x, const float* __restrict__ Wr) {
    int warp = threadIdx.x >> 5, lane = threadIdx.x & 31;
    int n = blockIdx.x * 8 + warp;
    if (n >= NT) return;
    const float* xr = x + (size_t)n * Dc;
    __half* xo = g_xh + (size_t)n * Dc;
    float acc[Ec];
#pragma unroll
    for (int e = 0; e < Ec; e++) acc[e] = 0.0f;
    for (int d0 = lane * 4; d0 < Dc; d0 += 128) {
        float4 xv = *(const float4*)(xr + d0);
        __half2 h01 = __floats2half2_rn(xv.x, xv.y);
        __half2 h23 = __floats2half2_rn(xv.z, xv.w);
        uint2 pk;
        pk.x = *(uint32_t*)&h01; pk.y = *(uint32_t*)&h23;
        *(uint2*)(xo + d0) = pk;
        float xs[4] = {xv.x, xv.y, xv.z, xv.w};
#pragma unroll
        for (int j = 0; j < 4; j++) {
            float4 w0 = *(const float4*)(Wr + (d0 + j) * Ec);
            float4 w1 = *(const float4*)(Wr + (d0 + j) * Ec + 4);
            acc[0] += xs[j] * w0.x; acc[1] += xs[j] * w0.y;
            acc[2] += xs[j] * w0.z; acc[3] += xs[j] * w0.w;
            acc[4] += xs[j] * w1.x; acc[5] += xs[j] * w1.y;
            acc[6] += xs[j] * w1.z; acc[7] += xs[j] * w1.w;
        }
    }
#pragma unroll
    for (int e = 0; e < Ec; e++)
#pragma unroll
        for (int o = 16; o > 0; o >>= 1)
            acc[e] += __shfl_xor_sync(0xffffffffu, acc[e], o);
    if (lane == 0) {
        float mx = acc[0];
#pragma unroll
        for (int e = 1; e < Ec; e++) mx = fmaxf(mx, acc[e]);
        float p[Ec], s = 0.0f;
#pragma unroll
        for (int e = 0; e < Ec; e++) { p[e] = __expf(acc[e] - mx); s += p[e]; }
        float inv = 1.0f / s;
        int i1 = 0;
#pragma unroll
        for (int e = 1; e < Ec; e++) if (p[e] > p[i1]) i1 = e;
        int i2 = (i1 == 0) ? 1 : 0;
#pragma unroll
        for (int e = 0; e < Ec; e++) if (e != i1 && p[e] > p[i2]) i2 = e;
        g_topi[2 * n] = i1;     g_topv[2 * n] = p[i1] * inv;
        g_topi[2 * n + 1] = i2; g_topv[2 * n + 1] = p[i2] * inv;
        atomicAdd(&g_cnt[i1], 1);
        atomicAdd(&g_cnt[i2], 1);
    }
}

// ---------------- launch 3: fused scan + scatter ----------------
__global__ void k_scansc() {
    __shared__ int soff[Ec];
    if (threadIdx.x == 0) {
        int o = 0;
#pragma unroll
        for (int e = 0; e < Ec; e++) {
            soff[e] = o;
            o += ((g_cnt[e] + TMp - 1) / TMp) * TMp;
        }
        if (blockIdx.x == 0) {
#pragma unroll
            for (int e = 0; e < Ec; e++) g_off[e] = soff[e];
            g_off[Ec] = o;
        }
    }
    __syncthreads();
    int n = blockIdx.x * blockDim.x + threadIdx.x;
    if (n >= NT) return;
#pragma unroll
    for (int k = 0; k < 2; k++) {
        int e = g_topi[2 * n + k];
        int pos = soff[e] + atomicAdd(&g_cur[e], 1);
        g_tok[pos] = n;
        g_gate[pos] = g_topv[2 * n + k];
        g_pos[2 * n + k] = pos;
    }
}

// ============ launch 4: FFN1 (R8 config) + embedded W2 conversion blocks ============
// grid (44, W2Y + 136): y < W2Y -> convert 2 rows of W2; else GEMM tile.
__global__ void __launch_bounds__(256, 2) k_ffn1(const float* __restrict__ W2) {
    if (blockIdx.y < W2Y) {
        // ---- conversion role: W2 [E][Hc][Dc] fp32 -> g_w2h [E][HP2][Dc] fp16 ----
        int bid = blockIdx.y * gridDim.x + blockIdx.x;   // 0 .. 11263
        int row = bid * 2 + (threadIdx.x >> 7);          // 0 .. 22527
        int col = (threadIdx.x & 127) * 8;
        int e = row / HP2, hp = row % HP2;
        __half* op = g_w2h + (size_t)row * Dc + col;
        __half2 v[4];
        if (hp < Hc) {
            const float* ip = W2 + ((size_t)e * Hc + hp) * Dc + col;
            float4 a = *(const float4*)ip, b = *(const float4*)(ip + 4);
            v[0] = __floats2half2_rn(a.x, a.y); v[1] = __floats2half2_rn(a.z, a.w);
            v[2] = __floats2half2_rn(b.x, b.y); v[3] = __floats2half2_rn(b.z, b.w);
        } else {
            v[0] = v[1] = v[2] = v[3] = __floats2half2_rn(0.f, 0.f);
        }
        *(uint4*)op = *(uint4*)v;
        return;
    }

    extern __shared__ __half sm[];
    int m0 = (blockIdx.y - W2Y) * 128;
    if (m0 >= g_off[Ec]) return;
    int e = 0;
#pragma unroll
    for (int i = 1; i < Ec; i++) if (m0 >= g_off[i]) e = i;
    int n0 = blockIdx.x * 64;

    int tid = threadIdx.x, wid = tid >> 5, lane = tid & 31;
    int wm = wid & 3, wn = wid >> 2;              // warp tile 32 x 32 (dual GEMM)
    int gi = lane >> 2, ti = lane & 3;
    uint32_t smb = smem_u32(sm);

    // loaders
    int rA = tid >> 1, chA = (tid & 1) * 32;      // A: 128 rows x 64 halves
    int rB = tid >> 2, cnB = (tid & 3) * 16;      // B: 64 rows x 64 halves
    int tok = g_tok[m0 + rA];
    const __half* srcA  = g_xh + (size_t)(tok < 0 ? 0 : tok) * Dc + chA;
    const __half* srcB1 = g_w1h + ((size_t)e * Dc + rB) * HP2 + n0 + cnB;
    const __half* srcB3 = g_w3h + ((size_t)e * Dc + rB) * HP2 + n0 + cnB;
    uint32_t dstA  = smb + (uint32_t)(rA * SA1 + chA) * 2;
    uint32_t dstB1 = smb + (uint32_t)(F1_B1OFF + rB * SBF1 + cnB) * 2;
    uint32_t dstB3 = smb + (uint32_t)(F1_B3OFF + rB * SBF1 + cnB) * 2;
    const uint32_t STGB = (uint32_t)F1_STGH * 2;

    auto issue = [&](int kc, int buf) {
        int k0 = kc * KCH;
        uint32_t so = buf * STGB;
        const __half* sA = srcA + k0;
        uint32_t dA = dstA + so;
        CP16(dA, sA); CP16(dA + 16, sA + 8); CP16(dA + 32, sA + 16); CP16(dA + 48, sA + 24);
        const __half* s1 = srcB1 + (size_t)k0 * HP2;
        uint32_t d1 = dstB1 + so;
        CP16(d1, s1); CP16(d1 + 16, s1 + 8);
        const __half* s3 = srcB3 + (size_t)k0 * HP2;
        uint32_t d3 = dstB3 + so;
        CP16(d3, s3); CP16(d3 + 16, s3 + 8);
    };

    // fragment bases
    int aRow = wm * 32 + (lane & 7) + 8 * ((lane >> 3) & 1);
    uint32_t aBase = smb + (uint32_t)(aRow * SA1 + 8 * (lane >> 4)) * 2;
    int bRowK = (lane & 7) + 8 * ((lane >> 3) & 1);
    uint32_t bBase = smb + (uint32_t)(F1_B1OFF + bRowK * SBF1 + wn * 32 + (lane >> 4) * 8) * 2;
    const uint32_t B3D = (uint32_t)(F1_B3OFF - F1_B1OFF) * 2;   // 9216

    float acc1[2][4][4], acc3[2][4][4];
#pragma unroll
    for (int mt = 0; mt < 2; mt++)
#pragma unroll
        for (int nt = 0; nt < 4; nt++)
#pragma unroll
            for (int j = 0; j < 4; j++) { acc1[mt][nt][j] = 0.f; acc3[mt][nt][j] = 0.f; }

    const int nc = Dc / KCH;   // 16
    issue(0, 0); CP_COMMIT();
    issue(1, 1); CP_COMMIT();

    for (int c = 0; c < nc; ++c) {
        if (c + 1 < nc) CP_WAIT1(); else CP_WAIT0();
        __syncthreads();
        if (c + 2 < nc) { issue(c + 2, (c + 2) % 3); CP_COMMIT(); }
        uint32_t so = (uint32_t)(c % 3) * STGB;
        uint32_t aA = aBase + so;
        uint32_t bB = bBase + so;
#pragma unroll
        for (int ks = 0; ks < 4; ks++) {
            uint32_t af[2][4];
            ldsm_x4(af[0], aA + ks * 32);
            ldsm_x4(af[1], aA + 2304 + ks * 32);        // +16 rows * 144B
#pragma unroll
            for (int np = 0; np < 2; np++) {            // nt pairs
                uint32_t bo = bB + ks * 2304 + np * 32; // +16 k-rows * 144B ; +16 cols
                uint32_t bf1[4], bf3[4];
                ldsm_x4t(bf1, bo);
                ldsm_x4t(bf3, bo + B3D);
                mma16(acc1[0][2 * np],     af[0], bf1);
                mma16(acc1[1][2 * np],     af[1], bf1);
                mma16(acc1[0][2 * np + 1], af[0], bf1 + 2);
                mma16(acc1[1][2 * np + 1], af[1], bf1 + 2);
                mma16(acc3[0][2 * np],     af[0], bf3);
                mma16(acc3[1][2 * np],     af[1], bf3);
                mma16(acc3[0][2 * np + 1], af[0], bf3 + 2);
                mma16(acc3[1][2 * np + 1], af[1], bf3 + 2);
            }
        }
    }

    // epilogue: silu(d1)*d3 -> g_h (fp16)
#pragma unroll
    for (int mt = 0; mt < 2; mt++) {
#pragma unroll
        for (int nt = 0; nt < 4; nt++) {
            int row = m0 + wm * 32 + mt * 16 + gi;
            int col = n0 + wn * 32 + nt * 8 + 2 * ti;
            const float* d1 = acc1[mt][nt];
            const float* d3 = acc3[mt][nt];
            float h0 = d1[0] / (1.0f + __expf(-d1[0])) * d3[0];
            float h1 = d1[1] / (1.0f + __expf(-d1[1])) * d3[1];
            float h2 = d1[2] / (1.0f + __expf(-d1[2])) * d3[2];
            float h3 = d1[3] / (1.0f + __expf(-d1[3])) * d3[3];
            *(__half2*)(g_h + (size_t)row * HP2 + col)       = __floats2half2_rn(h0, h1);
            *(__half2*)(g_h + (size_t)(row + 8) * HP2 + col) = __floats2half2_rn(h2, h3);
        }
    }
}

// ============ launch 5: FFN2  y = gate * (h @ W2), CTA 128x128, 2 CTA/SM (R8) ============
__global__ void __launch_bounds__(256, 2) k_ffn2() {
    extern __shared__ __half sm[];
    int m0 = blockIdx.y * 128;
    if (m0 >= g_off[Ec]) return;
    int e = 0;
#pragma unroll
    for (int i = 1; i < Ec; i++) if (m0 >= g_off[i]) e = i;
    int n0 = blockIdx.x * 128;

    int tid = threadIdx.x, wid = tid >> 5, lane = tid & 31;
    int wm = wid & 3, wn = wid >> 2;              // warp tile 32 x 64
    int gi = lane >> 2, ti = lane & 3;
    uint32_t smb = smem_u32(sm);

    int rA = tid >> 1, chA = (tid & 1) * 32;
    int rB = tid >> 2, cnB = (tid & 3) * 32;
    const __half* srcA = g_h + (size_t)(m0 + rA) * HP2 + chA;
    const __half* srcB = g_w2h + ((size_t)e * HP2 + rB) * Dc + n0 + cnB;
    uint32_t dstA = smb + (uint32_t)(rA * SA1 + chA) * 2;
    uint32_t dstB = smb + (uint32_t)(F2_BOFF + rB * SBF2 + cnB) * 2;
    const uint32_t STGB = (uint32_t)F2_STGH * 2;

    auto issue = [&](int kc, int buf) {
        int k0 = kc * KCH;
        uint32_t so = buf * STGB;
        const __half* sA = srcA + k0;
        uint32_t dA = dstA + so;
        CP16(dA, sA); CP16(dA + 16, sA + 8); CP16(dA + 32, sA + 16); CP16(dA + 48, sA + 24);
        const __half* sB = srcB + (size_t)k0 * Dc;
        uint32_t dB = dstB + so;
        CP16(dB, sB); CP16(dB + 16, sB + 8); CP16(dB + 32, sB + 16); CP16(dB + 48, sB + 24);
    };

    int aRow = wm * 32 + (lane & 7) + 8 * ((lane >> 3) & 1);
    uint32_t aBase = smb + (uint32_t)(aRow * SA1 + 8 * (lane >> 4)) * 2;
    int bRowK = (lane & 7) + 8 * ((lane >> 3) & 1);
    uint32_t bBase = smb + (uint32_t)(F2_BOFF + bRowK * SBF2 + wn * 64 + (lane >> 4) * 8) * 2;

    float acc[2][8][4];
#pragma unroll
    for (int mt = 0; mt < 2; mt++)
#pragma unroll
        for (int nt = 0; nt < 8; nt++)
#pragma unroll
            for (int j = 0; j < 4; j++) acc[mt][nt][j] = 0.f;

    const int nc = HP2 / KCH;   // 44
    issue(0, 0); CP_COMMIT();
    issue(1, 1); CP_COMMIT();

    for (int c = 0; c < nc; ++c) {
        if (c + 1 < nc) CP_WAIT1(); else CP_WAIT0();
        __syncthreads();
        if (c + 2 < nc) { issue(c + 2, (c + 2) % 3); CP_COMMIT(); }
        uint32_t so = (uint32_t)(c % 3) * STGB;
        uint32_t aA = aBase + so;
        uint32_t bB = bBase + so;
#pragma unroll
        for (int ks = 0; ks < 4; ks++) {
            uint32_t af[2][4];
            ldsm_x4(af[0], aA + ks * 32);
            ldsm_x4(af[1], aA + 2304 + ks * 32);
#pragma unroll
            for (int np = 0; np < 4; np++) {
                uint32_t bf[4];
                ldsm_x4t(bf, bB + ks * 4352 + np * 32);  // +16 k-rows * 272B ; +16 cols
                mma16(acc[0][2 * np],     af[0], bf);
                mma16(acc[1][2 * np],     af[1], bf);
                mma16(acc[0][2 * np + 1], af[0], bf + 2);
                mma16(acc[1][2 * np + 1], af[1], bf + 2);
            }
        }
    }

#pragma unroll
    for (int mt = 0; mt < 2; mt++) {
        int row = m0 + wm * 32 + mt * 16 + gi;
        float ga = g_gate[row];
        float gb = g_gate[row + 8];
#pragma unroll
        for (int nt = 0; nt < 8; nt++) {
            int col = n0 + wn * 64 + nt * 8 + 2 * ti;
            const float* d = acc[mt][nt];
            float2 o0, o1;
            o0.x = ga * d[0]; o0.y = ga * d[1];
            o1.x = gb * d[2]; o1.y = gb * d[3];
            *(float2*)(g_y + (size_t)row * Dc + col) = o0;
            *(float2*)(g_y + (size_t)(row + 8) * Dc + col) = o1;
        }
    }
}

// ---------------- launch 6: combine ----------------
__global__ void k_combine(float* __restrict__ out) {
    int i = blockIdx.x * blockDim.x + threadIdx.x;
    int n = i >> 8;
    int c = (i & 255) * 4;
    int p0 = g_pos[2 * n], p1 = g_pos[2 * n + 1];
    float4 a = *(const float4*)&g_y[(size_t)p0 * Dc + c];
    float4 b = *(const float4*)&g_y[(size_t)p1 * Dc + c];
    float4 o;
    o.x = a.x + b.x; o.y = a.y + b.y; o.z = a.z + b.z; o.w = a.w + b.w;
    *(float4*)(out + (size_t)n * Dc + c) = o;
}

// ---------------- launch ----------------
extern "C" void kernel_launch(void* const* d_in, const int* in_sizes, int n_in,
                              void* d_out, int out_size) {
    const float* x  = (const float*)d_in[0];
    const float* Wr = (const float*)d_in[1];
    const float* W1 = (const float*)d_in[2];
    const float* W2 = (const float*)d_in[3];
    const float* W3 = (const float*)d_in[4];
    float* out = (float*)d_out;

    cudaFuncSetAttribute(k_ffn1, cudaFuncAttributeMaxDynamicSharedMemorySize, F1_SMEM);
    cudaFuncSetAttribute(k_ffn2, cudaFuncAttributeMaxDynamicSharedMemorySize, F2_SMEM);

    k_prep<<<Ec * Dc, 256>>>(W1, W3);                                  // 1
    k_routerx<<<NT / 8, 256>>>(x, Wr);                                 // 2
    k_scansc<<<NT / 256, 256>>>();                                     // 3
    k_ffn1<<<dim3(HP2 / 64, W2Y + MMAX / 128), 256, F1_SMEM>>>(W2);    // 4  <- profiled (GEMM + W2 convert)
    k_ffn2<<<dim3(Dc / 128, MMAX / 128), 256, F2_SMEM>>>();            // 5
    k_combine<<<(NT * (Dc / 4)) / 256, 256>>>(out);                    // 6
}

// round 11
// speedup vs baseline: 1.2366x; 1.0147x over previous
#include <cuda_runtime.h>
#include <cuda_fp16.h>
#include <cstdint>

// ---------------- problem constants ----------------
#define Dc   1024
#define Ec   8
#define Hc   2730
#define HP2  2816            // H padded to 22*128
#define NT   8192
#define TMp  128             // per-expert row padding
#define MMAX (2*NT + Ec*TMp) // 17408
#define KCH  64              // K halves per pipeline chunk (4 x k16)

// smem strides (halves)
#define SA1  72              // A row stride (64 K + 8 pad)  = 144 B
#define SBF1 72              // FFN1 B row stride (64 N + 8 pad)
#define SBF2 136             // FFN2 B row stride (128 N + 8 pad) = 272 B

// FFN1 stage (halves): A[128][72]=9216, B1[64][72]=4608, B3[64][72]=4608
#define F1_B1OFF 9216
#define F1_B3OFF 13824
#define F1_STGH  18432
#define F1_SMEM  (3 * F1_STGH * 2)    // 110592 B  (2 CTAs/SM)
// FFN2 stage: A[128][72]=9216, B[64][136]=8704
#define F2_BOFF  9216
#define F2_STGH  17920
#define F2_SMEM  (3 * F2_STGH * 2)    // 107520 B  (2 CTAs/SM)

// ---------------- device scratch ----------------
__device__ int    g_cnt[Ec];
__device__ int    g_cur[Ec];
__device__ int    g_off[Ec + 1];
__device__ int    g_tok[MMAX];
__device__ float  g_gate[MMAX];
__device__ int    g_topi[NT * 2];
__device__ float  g_topv[NT * 2];
__device__ __half g_w1h[(size_t)Ec * Dc * HP2];   // W1 fp16 [E][Dc][HP2]
__device__ __half g_w3h[(size_t)Ec * Dc * HP2];   // W3 fp16
__device__ __half g_w2h[(size_t)Ec * HP2 * Dc];   // W2 fp16 [E][HP2][Dc]
__device__ __half g_xh[(size_t)NT * Dc];          // x fp16
__device__ __half g_h[(size_t)MMAX * HP2];        // activations fp16

// ---------------- helpers ----------------
__device__ __forceinline__ uint32_t smem_u32(const void* p) {
    uint32_t a;
    asm("{ .reg .u64 t; cvta.to.shared.u64 t, %1; cvt.u32.u64 %0, t; }" : "=r"(a) : "l"(p));
    return a;
}
#define CP16(dst, src) asm volatile("cp.async.cg.shared.global [%0], [%1], 16;" :: "r"(dst), "l"(src) : "memory")
#define CP_COMMIT()    asm volatile("cp.async.commit_group;" ::: "memory")
#define CP_WAIT0()     asm volatile("cp.async.wait_group 0;" ::: "memory")
#define CP_WAIT1()     asm volatile("cp.async.wait_group 1;" ::: "memory")

__device__ __forceinline__ void ldsm_x4(uint32_t* r, uint32_t a) {
    asm volatile("ldmatrix.sync.aligned.m8n8.x4.shared.b16 {%0,%1,%2,%3}, [%4];"
        : "=r"(r[0]), "=r"(r[1]), "=r"(r[2]), "=r"(r[3]) : "r"(a));
}
__device__ __forceinline__ void ldsm_x4t(uint32_t* r, uint32_t a) {
    asm volatile("ldmatrix.sync.aligned.m8n8.x4.trans.shared.b16 {%0,%1,%2,%3}, [%4];"
        : "=r"(r[0]), "=r"(r[1]), "=r"(r[2]), "=r"(r[3]) : "r"(a));
}
__device__ __forceinline__ void mma16(float* d, const uint32_t* a, const uint32_t* b) {
    asm volatile(
        "mma.sync.aligned.m16n8k16.row.col.f32.f16.f16.f32 "
        "{%0,%1,%2,%3}, {%4,%5,%6,%7}, {%8,%9}, {%0,%1,%2,%3};"
        : "+f"(d[0]), "+f"(d[1]), "+f"(d[2]), "+f"(d[3])
        : "r"(a[0]), "r"(a[1]), "r"(a[2]), "r"(a[3]), "r"(b[0]), "r"(b[1]));
}

// ---------------- launch 1: convert W1,W3 to fp16 + zero bookkeeping + zero out ----------------
__global__ void k_prep(const float* __restrict__ W1, const float* __restrict__ W3,
                       float* __restrict__ out) {
    int gid = blockIdx.x * blockDim.x + threadIdx.x;
    if (gid < Ec) { g_cnt[gid] = 0; g_cur[gid] = 0; }
    if (gid < MMAX) { g_tok[gid] = -1; g_gate[gid] = 0.0f; }

    // zero out: 8192 blocks x 1024 floats = 8.4M floats
    {
        float4 z = make_float4(0.f, 0.f, 0.f, 0.f);
        *(float4*)(out + (size_t)blockIdx.x * 1024 + threadIdx.x * 4) = z;
    }

    int row = blockIdx.x;                       // 0 .. E*Dc-1
    const float* i1 = W1 + (size_t)row * Hc;
    const float* i3 = W3 + (size_t)row * Hc;
    __half* o1 = g_w1h + (size_t)row * HP2;
    __half* o3 = g_w3h + (size_t)row * HP2;
    for (int u = threadIdx.x; u < HP2 / 8; u += 256) {
        int j = u * 8;
        __half2 v1[4], v3[4];
        if (j + 8 <= Hc) {
            float2 a0 = *(const float2*)(i1 + j),     a1 = *(const float2*)(i1 + j + 2);
            float2 a2 = *(const float2*)(i1 + j + 4), a3 = *(const float2*)(i1 + j + 6);
            v1[0] = __floats2half2_rn(a0.x, a0.y); v1[1] = __floats2half2_rn(a1.x, a1.y);
            v1[2] = __floats2half2_rn(a2.x, a2.y); v1[3] = __floats2half2_rn(a3.x, a3.y);
            float2 b0 = *(const float2*)(i3 + j),     b1 = *(const float2*)(i3 + j + 2);
            float2 b2 = *(const float2*)(i3 + j + 4), b3 = *(const float2*)(i3 + j + 6);
            v3[0] = __floats2half2_rn(b0.x, b0.y); v3[1] = __floats2half2_rn(b1.x, b1.y);
            v3[2] = __floats2half2_rn(b2.x, b2.y); v3[3] = __floats2half2_rn(b3.x, b3.y);
        } else {
#pragma unroll
            for (int t = 0; t < 4; t++) {
                int c0 = j + 2 * t, c1 = j + 2 * t + 1;
                float f0 = (c0 < Hc) ? i1[c0] : 0.f;
                float f1 = (c1 < Hc) ? i1[c1] : 0.f;
                v1[t] = __floats2half2_rn(f0, f1);
                float g0 = (c0 < Hc) ? i3[c0] : 0.f;
                float g1 = (c1 < Hc) ? i3[c1] : 0.f;
                v3[t] = __floats2half2_rn(g0, g1);
            }
        }
        *(uint4*)(o1 + j) = *(uint4*)v1;
        *(uint4*)(o3 + j) = *(uint4*)v3;
    }
}

// ---------------- launch 5: convert W2 to fp16 (row-padded) ----------------
__global__ void k_w2h(const float* __restrict__ in) {
    int row = blockIdx.x;                       // 0 .. E*HP2-1
    int e = row / HP2, hp = row % HP2;
    __half* op = g_w2h + (size_t)row * Dc;
    int j = threadIdx.x * 8;                    // 128 threads * 8 = 1024
    __half2 v[4];
    if (hp < Hc) {
        const float* ip = in + ((size_t)e * Hc + hp) * Dc + j;
        float4 a = *(const float4*)ip, b = *(const float4*)(ip + 4);
        v[0] = __floats2half2_rn(a.x, a.y); v[1] = __floats2half2_rn(a.z, a.w);
        v[2] = __floats2half2_rn(b.x, b.y); v[3] = __floats2half2_rn(b.z, b.w);
    } else {
        v[0] = v[1] = v[2] = v[3] = __floats2half2_rn(0.f, 0.f);
    }
    *(uint4*)(op + j) = *(uint4*)v;
}

// ---------------- launch 2: router (+ x -> fp16) ----------------
__global__ void k_routerx(const float* __restrict__ x, const float* __restrict__ Wr) {
    int warp = threadIdx.x >> 5, lane = threadIdx.x & 31;
    int n = blockIdx.x * 8 + warp;
    if (n >= NT) return;
    const float* xr = x + (size_t)n * Dc;
    __half* xo = g_xh + (size_t)n * Dc;
    float acc[Ec];
#pragma unroll
    for (int e = 0; e < Ec; e++) acc[e] = 0.0f;
    for (int d0 = lane * 4; d0 < Dc; d0 += 128) {
        float4 xv = *(const float4*)(xr + d0);
        __half2 h01 = __floats2half2_rn(xv.x, xv.y);
        __half2 h23 = __floats2half2_rn(xv.z, xv.w);
        uint2 pk;
        pk.x = *(uint32_t*)&h01; pk.y = *(uint32_t*)&h23;
        *(uint2*)(xo + d0) = pk;
        float xs[4] = {xv.x, xv.y, xv.z, xv.w};
#pragma unroll
        for (int j = 0; j < 4; j++) {
            float4 w0 = *(const float4*)(Wr + (d0 + j) * Ec);
            float4 w1 = *(const float4*)(Wr + (d0 + j) * Ec + 4);
            acc[0] += xs[j] * w0.x; acc[1] += xs[j] * w0.y;
            acc[2] += xs[j] * w0.z; acc[3] += xs[j] * w0.w;
            acc[4] += xs[j] * w1.x; acc[5] += xs[j] * w1.y;
            acc[6] += xs[j] * w1.z; acc[7] += xs[j] * w1.w;
        }
    }
#pragma unroll
    for (int e = 0; e < Ec; e++)
#pragma unroll
        for (int o = 16; o > 0; o >>= 1)
            acc[e] += __shfl_xor_sync(0xffffffffu, acc[e], o);
    if (lane == 0) {
        float mx = acc[0];
#pragma unroll
        for (int e = 1; e < Ec; e++) mx = fmaxf(mx, acc[e]);
        float p[Ec], s = 0.0f;
#pragma unroll
        for (int e = 0; e < Ec; e++) { p[e] = __expf(acc[e] - mx); s += p[e]; }
        float inv = 1.0f / s;
        int i1 = 0;
#pragma unroll
        for (int e = 1; e < Ec; e++) if (p[e] > p[i1]) i1 = e;
        int i2 = (i1 == 0) ? 1 : 0;
#pragma unroll
        for (int e = 0; e < Ec; e++) if (e != i1 && p[e] > p[i2]) i2 = e;
        g_topi[2 * n] = i1;     g_topv[2 * n] = p[i1] * inv;
        g_topi[2 * n + 1] = i2; g_topv[2 * n + 1] = p[i2] * inv;
        atomicAdd(&g_cnt[i1], 1);
        atomicAdd(&g_cnt[i2], 1);
    }
}

// ---------------- launch 3: fused scan + scatter ----------------
__global__ void k_scansc() {
    __shared__ int soff[Ec];
    if (threadIdx.x == 0) {
        int o = 0;
#pragma unroll
        for (int e = 0; e < Ec; e++) {
            soff[e] = o;
            o += ((g_cnt[e] + TMp - 1) / TMp) * TMp;
        }
        if (blockIdx.x == 0) {
#pragma unroll
            for (int e = 0; e < Ec; e++) g_off[e] = soff[e];
            g_off[Ec] = o;
        }
    }
    __syncthreads();
    int n = blockIdx.x * blockDim.x + threadIdx.x;
    if (n >= NT) return;
#pragma unroll
    for (int k = 0; k < 2; k++) {
        int e = g_topi[2 * n + k];
        int pos = soff[e] + atomicAdd(&g_cur[e], 1);
        g_tok[pos] = n;
        g_gate[pos] = g_topv[2 * n + k];
    }
}

// ============ launch 4: FFN1  h = silu(X@W1) * (X@W3), CTA 128x64, 2 CTA/SM (R8) ============
__global__ void __launch_bounds__(256, 2) k_ffn1() {
    extern __shared__ __half sm[];
    int m0 = blockIdx.y * 128;
    if (m0 >= g_off[Ec]) return;
    int e = 0;
#pragma unroll
    for (int i = 1; i < Ec; i++) if (m0 >= g_off[i]) e = i;
    int n0 = blockIdx.x * 64;

    int tid = threadIdx.x, wid = tid >> 5, lane = tid & 31;
    int wm = wid & 3, wn = wid >> 2;              // warp tile 32 x 32 (dual GEMM)
    int gi = lane >> 2, ti = lane & 3;
    uint32_t smb = smem_u32(sm);

    int rA = tid >> 1, chA = (tid & 1) * 32;      // A: 128 rows x 64 halves
    int rB = tid >> 2, cnB = (tid & 3) * 16;      // B: 64 rows x 64 halves
    int tok = g_tok[m0 + rA];
    const __half* srcA  = g_xh + (size_t)(tok < 0 ? 0 : tok) * Dc + chA;
    const __half* srcB1 = g_w1h + ((size_t)e * Dc + rB) * HP2 + n0 + cnB;
    const __half* srcB3 = g_w3h + ((size_t)e * Dc + rB) * HP2 + n0 + cnB;
    uint32_t dstA  = smb + (uint32_t)(rA * SA1 + chA) * 2;
    uint32_t dstB1 = smb + (uint32_t)(F1_B1OFF + rB * SBF1 + cnB) * 2;
    uint32_t dstB3 = smb + (uint32_t)(F1_B3OFF + rB * SBF1 + cnB) * 2;
    const uint32_t STGB = (uint32_t)F1_STGH * 2;

    auto issue = [&](int kc, int buf) {
        int k0 = kc * KCH;
        uint32_t so = buf * STGB;
        const __half* sA = srcA + k0;
        uint32_t dA = dstA + so;
        CP16(dA, sA); CP16(dA + 16, sA + 8); CP16(dA + 32, sA + 16); CP16(dA + 48, sA + 24);
        const __half* s1 = srcB1 + (size_t)k0 * HP2;
        uint32_t d1 = dstB1 + so;
        CP16(d1, s1); CP16(d1 + 16, s1 + 8);
        const __half* s3 = srcB3 + (size_t)k0 * HP2;
        uint32_t d3 = dstB3 + so;
        CP16(d3, s3); CP16(d3 + 16, s3 + 8);
    };

    int aRow = wm * 32 + (lane & 7) + 8 * ((lane >> 3) & 1);
    uint32_t aBase = smb + (uint32_t)(aRow * SA1 + 8 * (lane >> 4)) * 2;
    int bRowK = (lane & 7) + 8 * ((lane >> 3) & 1);
    uint32_t bBase = smb + (uint32_t)(F1_B1OFF + bRowK * SBF1 + wn * 32 + (lane >> 4) * 8) * 2;
    const uint32_t B3D = (uint32_t)(F1_B3OFF - F1_B1OFF) * 2;   // 9216

    float acc1[2][4][4], acc3[2][4][4];
#pragma unroll
    for (int mt = 0; mt < 2; mt++)
#pragma unroll
        for (int nt = 0; nt < 4; nt++)
#pragma unroll
            for (int j = 0; j < 4; j++) { acc1[mt][nt][j] = 0.f; acc3[mt][nt][j] = 0.f; }

    const int nc = Dc / KCH;   // 16
    issue(0, 0); CP_COMMIT();
    issue(1, 1); CP_COMMIT();

    for (int c = 0; c < nc; ++c) {
        if (c + 1 < nc) CP_WAIT1(); else CP_WAIT0();
        __syncthreads();
        if (c + 2 < nc) { issue(c + 2, (c + 2) % 3); CP_COMMIT(); }
        uint32_t so = (uint32_t)(c % 3) * STGB;
        uint32_t aA = aBase + so;
        uint32_t bB = bBase + so;
#pragma unroll
        for (int ks = 0; ks < 4; ks++) {
            uint32_t af[2][4];
            ldsm_x4(af[0], aA + ks * 32);
            ldsm_x4(af[1], aA + 2304 + ks * 32);        // +16 rows * 144B
#pragma unroll
            for (int np = 0; np < 2; np++) {            // nt pairs
                uint32_t bo = bB + ks * 2304 + np * 32; // +16 k-rows * 144B ; +16 cols
                uint32_t bf1[4], bf3[4];
                ldsm_x4t(bf1, bo);
                ldsm_x4t(bf3, bo + B3D);
                mma16(acc1[0][2 * np],     af[0], bf1);
                mma16(acc1[1][2 * np],     af[1], bf1);
                mma16(acc1[0][2 * np + 1], af[0], bf1 + 2);
                mma16(acc1[1][2 * np + 1], af[1], bf1 + 2);
                mma16(acc3[0][2 * np],     af[0], bf3);
                mma16(acc3[1][2 * np],     af[1], bf3);
                mma16(acc3[0][2 * np + 1], af[0], bf3 + 2);
                mma16(acc3[1][2 * np + 1], af[1], bf3 + 2);
            }
        }
    }

    // epilogue: silu(d1)*d3 -> g_h (fp16)
#pragma unroll
    for (int mt = 0; mt < 2; mt++) {
#pragma unroll
        for (int nt = 0; nt < 4; nt++) {
            int row = m0 + wm * 32 + mt * 16 + gi;
            int col = n0 + wn * 32 + nt * 8 + 2 * ti;
            const float* d1 = acc1[mt][nt];
            const float* d3 = acc3[mt][nt];
            float h0 = d1[0] / (1.0f + __expf(-d1[0])) * d3[0];
            float h1 = d1[1] / (1.0f + __expf(-d1[1])) * d3[1];
            float h2 = d1[2] / (1.0f + __expf(-d1[2])) * d3[2];
            float h3 = d1[3] / (1.0f + __expf(-d1[3])) * d3[3];
            *(__half2*)(g_h + (size_t)row * HP2 + col)       = __floats2half2_rn(h0, h1);
            *(__half2*)(g_h + (size_t)(row + 8) * HP2 + col) = __floats2half2_rn(h2, h3);
        }
    }
}

// ============ launch 6: FFN2  out += gate * (h @ W2), CTA 128x128, 2 CTA/SM ============
// combine is fused: epilogue atomically adds gated rows into out[token].
// Exactly two fp32 addends per out element -> order-independent, deterministic.
__global__ void __launch_bounds__(256, 2) k_ffn2(float* __restrict__ out) {
    extern __shared__ __half sm[];
    int m0 = blockIdx.y * 128;
    if (m0 >= g_off[Ec]) return;
    int e = 0;
#pragma unroll
    for (int i = 1; i < Ec; i++) if (m0 >= g_off[i]) e = i;
    int n0 = blockIdx.x * 128;

    int tid = threadIdx.x, wid = tid >> 5, lane = tid & 31;
    int wm = wid & 3, wn = wid >> 2;              // warp tile 32 x 64
    int gi = lane >> 2, ti = lane & 3;
    uint32_t smb = smem_u32(sm);

    int rA = tid >> 1, chA = (tid & 1) * 32;
    int rB = tid >> 2, cnB = (tid & 3) * 32;
    const __half* srcA = g_h + (size_t)(m0 + rA) * HP2 + chA;
    const __half* srcB = g_w2h + ((size_t)e * HP2 + rB) * Dc + n0 + cnB;
    uint32_t dstA = smb + (uint32_t)(rA * SA1 + chA) * 2;
    uint32_t dstB = smb + (uint32_t)(F2_BOFF + rB * SBF2 + cnB) * 2;
    const uint32_t STGB = (uint32_t)F2_STGH * 2;

    auto issue = [&](int kc, int buf) {
        int k0 = kc * KCH;
        uint32_t so = buf * STGB;
        const __half* sA = srcA + k0;
        uint32_t dA = dstA + so;
        CP16(dA, sA); CP16(dA + 16, sA + 8); CP16(dA + 32, sA + 16); CP16(dA + 48, sA + 24);
        const __half* sB = srcB + (size_t)k0 * Dc;
        uint32_t dB = dstB + so;
        CP16(dB, sB); CP16(dB + 16, sB + 8); CP16(dB + 32, sB + 16); CP16(dB + 48, sB + 24);
    };

    int aRow = wm * 32 + (lane & 7) + 8 * ((lane >> 3) & 1);
    uint32_t aBase = smb + (uint32_t)(aRow * SA1 + 8 * (lane >> 4)) * 2;
    int bRowK = (lane & 7) + 8 * ((lane >> 3) & 1);
    uint32_t bBase = smb + (uint32_t)(F2_BOFF + bRowK * SBF2 + wn * 64 + (lane >> 4) * 8) * 2;

    float acc[2][8][4];
#pragma unroll
    for (int mt = 0; mt < 2; mt++)
#pragma unroll
        for (int nt = 0; nt < 8; nt++)
#pragma unroll
            for (int j = 0; j < 4; j++) acc[mt][nt][j] = 0.f;

    const int nc = HP2 / KCH;   // 44
    issue(0, 0); CP_COMMIT();
    issue(1, 1); CP_COMMIT();

    for (int c = 0; c < nc; ++c) {
        if (c + 1 < nc) CP_WAIT1(); else CP_WAIT0();
        __syncthreads();
        if (c + 2 < nc) { issue(c + 2, (c + 2) % 3); CP_COMMIT(); }
        uint32_t so = (uint32_t)(c % 3) * STGB;
        uint32_t aA = aBase + so;
        uint32_t bB = bBase + so;
#pragma unroll
        for (int ks = 0; ks < 4; ks++) {
            uint32_t af[2][4];
            ldsm_x4(af[0], aA + ks * 32);
            ldsm_x4(af[1], aA + 2304 + ks * 32);
#pragma unroll
            for (int np = 0; np < 4; np++) {
                uint32_t bf[4];
                ldsm_x4t(bf, bB + ks * 4352 + np * 32);  // +16 k-rows * 272B ; +16 cols
                mma16(acc[0][2 * np],     af[0], bf);
                mma16(acc[1][2 * np],     af[1], bf);
                mma16(acc[0][2 * np + 1], af[0], bf + 2);
                mma16(acc[1][2 * np + 1], af[1], bf + 2);
            }
        }
    }

    // epilogue: fused combine -> atomicAdd into out[token]
#pragma unroll
    for (int mt = 0; mt < 2; mt++) {
        int row = m0 + wm * 32 + mt * 16 + gi;
        int tok0 = g_tok[row];
        int tok1 = g_tok[row + 8];
        float ga = g_gate[row];
        float gb = g_gate[row + 8];
        float* o0 = out + (size_t)(tok0 < 0 ? 0 : tok0) * Dc;
        float* o1 = out + (size_t)(tok1 < 0 ? 0 : tok1) * Dc;
#pragma unroll
        for (int nt = 0; nt < 8; nt++) {
            int col = n0 + wn * 64 + nt * 8 + 2 * ti;
            const float* d = acc[mt][nt];
            if (tok0 >= 0) {
                atomicAdd(o0 + col,     ga * d[0]);
                atomicAdd(o0 + col + 1, ga * d[1]);
            }
            if (tok1 >= 0) {
                atomicAdd(o1 + col,     gb * d[2]);
                atomicAdd(o1 + col + 1, gb * d[3]);
            }
        }
    }
}

// ---------------- launch ----------------
extern "C" void kernel_launch(void* const* d_in, const int* in_sizes, int n_in,
                              void* d_out, int out_size) {
    const float* x  = (const float*)d_in[0];
    const float* Wr = (const float*)d_in[1];
    const float* W1 = (const float*)d_in[2];
    const float* W2 = (const float*)d_in[3];
    const float* W3 = (const float*)d_in[4];
    float* out = (float*)d_out;

    cudaFuncSetAttribute(k_ffn1, cudaFuncAttributeMaxDynamicSharedMemorySize, F1_SMEM);
    cudaFuncSetAttribute(k_ffn2, cudaFuncAttributeMaxDynamicSharedMemorySize, F2_SMEM);

    k_prep<<<Ec * Dc, 256>>>(W1, W3, out);                     // 1 (also zeroes out)
    k_routerx<<<NT / 8, 256>>>(x, Wr);                         // 2
    k_scansc<<<NT / 256, 256>>>();                             // 3
    k_ffn1<<<dim3(HP2 / 64, MMAX / 128), 256, F1_SMEM>>>();    // 4  <- profiled
    k_w2h<<<Ec * HP2, 128>>>(W2);                              // 5
    k_ffn2<<<dim3(Dc / 128, MMAX / 128), 256, F2_SMEM>>>(out); // 6 (fused combine)
}

// round 12
// speedup vs baseline: 1.2423x; 1.0046x over previous
#include <cuda_runtime.h>
#include <cuda_fp16.h>
#include <cstdint>

// ---------------- problem constants ----------------
#define Dc   1024
#define Ec   8
#define Hc   2730
#define HP2  2816            // H padded to 22*128
#define NT   8192
#define TMp  128             // per-expert row padding
#define MMAX (2*NT + Ec*TMp) // 17408
#define KCH  64              // K halves per pipeline chunk (4 x k16)

// smem strides (halves)
#define SA1  72              // A row stride (64 K + 8 pad)  = 144 B
#define SBF1 72              // FFN1 B row stride (64 N + 8 pad)
#define SBF2 136             // FFN2 B row stride (128 N + 8 pad) = 272 B

// FFN1 stage (halves): A[128][72]=9216, B1[64][72]=4608, B3[64][72]=4608
#define F1_B1OFF 9216
#define F1_B3OFF 13824
#define F1_STGH  18432
#define F1_SMEM  (3 * F1_STGH * 2)    // 110592 B  (2 CTAs/SM)
// FFN2 stage: A[128][72]=9216, B[64][136]=8704
#define F2_BOFF  9216
#define F2_STGH  17920
#define F2_SMEM  (3 * F2_STGH * 2)    // 107520 B  (2 CTAs/SM)

// k_prep roles: blocks [0, PREP13) = W1/W3 rows; [PREP13, PREP13+PREPW2) = W2 rows (2 each)
#define PREP13  (Ec * Dc)             // 8192
#define PREPW2  (Ec * HP2 / 2)        // 11264

// ---------------- device scratch ----------------
__device__ int    g_cnt[Ec];
__device__ int    g_cur[Ec];
__device__ int    g_off[Ec + 1];
__device__ int    g_tok[MMAX];
__device__ float  g_gate[MMAX];
__device__ int    g_topi[NT * 2];
__device__ float  g_topv[NT * 2];
__device__ __half g_w1h[(size_t)Ec * Dc * HP2];   // W1 fp16 [E][Dc][HP2]
__device__ __half g_w3h[(size_t)Ec * Dc * HP2];   // W3 fp16
__device__ __half g_w2h[(size_t)Ec * HP2 * Dc];   // W2 fp16 [E][HP2][Dc]
__device__ __half g_xh[(size_t)NT * Dc];          // x fp16
__device__ __half g_h[(size_t)MMAX * HP2];        // activations fp16

// ---------------- helpers ----------------
__device__ __forceinline__ uint32_t smem_u32(const void* p) {
    uint32_t a;
    asm("{ .reg .u64 t; cvta.to.shared.u64 t, %1; cvt.u32.u64 %0, t; }" : "=r"(a) : "l"(p));
    return a;
}
#define CP16(dst, src) asm volatile("cp.async.cg.shared.global [%0], [%1], 16;" :: "r"(dst), "l"(src) : "memory")
#define CP_COMMIT()    asm volatile("cp.async.commit_group;" ::: "memory")
#define CP_WAIT0()     asm volatile("cp.async.wait_group 0;" ::: "memory")
#define CP_WAIT1()     asm volatile("cp.async.wait_group 1;" ::: "memory")

__device__ __forceinline__ void ldsm_x4(uint32_t* r, uint32_t a) {
    asm volatile("ldmatrix.sync.aligned.m8n8.x4.shared.b16 {%0,%1,%2,%3}, [%4];"
        : "=r"(r[0]), "=r"(r[1]), "=r"(r[2]), "=r"(r[3]) : "r"(a));
}
__device__ __forceinline__ void ldsm_x4t(uint32_t* r, uint32_t a) {
    asm volatile("ldmatrix.sync.aligned.m8n8.x4.trans.shared.b16 {%0,%1,%2,%3}, [%4];"
        : "=r"(r[0]), "=r"(r[1]), "=r"(r[2]), "=r"(r[3]) : "r"(a));
}
__device__ __forceinline__ void mma16(float* d, const uint32_t* a, const uint32_t* b) {
    asm volatile(
        "mma.sync.aligned.m16n8k16.row.col.f32.f16.f16.f32 "
        "{%0,%1,%2,%3}, {%4,%5,%6,%7}, {%8,%9}, {%0,%1,%2,%3};"
        : "+f"(d[0]), "+f"(d[1]), "+f"(d[2]), "+f"(d[3])
        : "r"(a[0]), "r"(a[1]), "r"(a[2]), "r"(a[3]), "r"(b[0]), "r"(b[1]));
}

// ---------------- launch 1: ALL weight converts + zero out + bookkeeping ----------------
__global__ void k_prep(const float* __restrict__ W1, const float* __restrict__ W3,
                       const float* __restrict__ W2, float* __restrict__ out) {
    if (blockIdx.x < PREP13) {
        // ---- role A: one W1/W3 row + zero-out slice + bookkeeping ----
        int gid = blockIdx.x * blockDim.x + threadIdx.x;
        if (gid < Ec) { g_cnt[gid] = 0; g_cur[gid] = 0; }
        if (gid < MMAX) { g_tok[gid] = -1; g_gate[gid] = 0.0f; }

        // zero out: 8192 blocks x 1024 floats
        {
            float4 z = make_float4(0.f, 0.f, 0.f, 0.f);
            *(float4*)(out + (size_t)blockIdx.x * 1024 + threadIdx.x * 4) = z;
        }

        int row = blockIdx.x;                       // 0 .. E*Dc-1
        const float* i1 = W1 + (size_t)row * Hc;
        const float* i3 = W3 + (size_t)row * Hc;
        __half* o1 = g_w1h + (size_t)row * HP2;
        __half* o3 = g_w3h + (size_t)row * HP2;
        for (int u = threadIdx.x; u < HP2 / 8; u += 256) {
            int j = u * 8;
            __half2 v1[4], v3[4];
            if (j + 8 <= Hc) {
                float2 a0 = *(const float2*)(i1 + j),     a1 = *(const float2*)(i1 + j + 2);
                float2 a2 = *(const float2*)(i1 + j + 4), a3 = *(const float2*)(i1 + j + 6);
                v1[0] = __floats2half2_rn(a0.x, a0.y); v1[1] = __floats2half2_rn(a1.x, a1.y);
                v1[2] = __floats2half2_rn(a2.x, a2.y); v1[3] = __floats2half2_rn(a3.x, a3.y);
                float2 b0 = *(const float2*)(i3 + j),     b1 = *(const float2*)(i3 + j + 2);
                float2 b2 = *(const float2*)(i3 + j + 4), b3 = *(const float2*)(i3 + j + 6);
                v3[0] = __floats2half2_rn(b0.x, b0.y); v3[1] = __floats2half2_rn(b1.x, b1.y);
                v3[2] = __floats2half2_rn(b2.x, b2.y); v3[3] = __floats2half2_rn(b3.x, b3.y);
            } else {
#pragma unroll
                for (int t = 0; t < 4; t++) {
                    int c0 = j + 2 * t, c1 = j + 2 * t + 1;
                    float f0 = (c0 < Hc) ? i1[c0] : 0.f;
                    float f1 = (c1 < Hc) ? i1[c1] : 0.f;
                    v1[t] = __floats2half2_rn(f0, f1);
                    float g0 = (c0 < Hc) ? i3[c0] : 0.f;
                    float g1 = (c1 < Hc) ? i3[c1] : 0.f;
                    v3[t] = __floats2half2_rn(g0, g1);
                }
            }
            *(uint4*)(o1 + j) = *(uint4*)v1;
            *(uint4*)(o3 + j) = *(uint4*)v3;
        }
    } else {
        // ---- role B: two W2 rows: [E][Hc][Dc] fp32 -> [E][HP2][Dc] fp16 ----
        int bid = blockIdx.x - PREP13;              // 0 .. PREPW2-1
        int row = bid * 2 + (threadIdx.x >> 7);     // 0 .. E*HP2-1
        int col = (threadIdx.x & 127) * 8;
        int e = row / HP2, hp = row % HP2;
        __half* op = g_w2h + (size_t)row * Dc + col;
        __half2 v[4];
        if (hp < Hc) {
            const float* ip = W2 + ((size_t)e * Hc + hp) * Dc + col;
            float4 a = *(const float4*)ip, b = *(const float4*)(ip + 4);
            v[0] = __floats2half2_rn(a.x, a.y); v[1] = __floats2half2_rn(a.z, a.w);
            v[2] = __floats2half2_rn(b.x, b.y); v[3] = __floats2half2_rn(b.z, b.w);
        } else {
            v[0] = v[1] = v[2] = v[3] = __floats2half2_rn(0.f, 0.f);
        }
        *(uint4*)op = *(uint4*)v;
    }
}

// ---------------- launch 2: router (+ x -> fp16) ----------------
__global__ void k_routerx(const float* __restrict__ x, const float* __restrict__ Wr) {
    int warp = threadIdx.x >> 5, lane = threadIdx.x & 31;
    int n = blockIdx.x * 8 + warp;
    if (n >= NT) return;
    const float* xr = x + (size_t)n * Dc;
    __half* xo = g_xh + (size_t)n * Dc;
    float acc[Ec];
#pragma unroll
    for (int e = 0; e < Ec; e++) acc[e] = 0.0f;
    for (int d0 = lane * 4; d0 < Dc; d0 += 128) {
        float4 xv = *(const float4*)(xr + d0);
        __half2 h01 = __floats2half2_rn(xv.x, xv.y);
        __half2 h23 = __floats2half2_rn(xv.z, xv.w);
        uint2 pk;
        pk.x = *(uint32_t*)&h01; pk.y = *(uint32_t*)&h23;
        *(uint2*)(xo + d0) = pk;
        float xs[4] = {xv.x, xv.y, xv.z, xv.w};
#pragma unroll
        for (int j = 0; j < 4; j++) {
            float4 w0 = *(const float4*)(Wr + (d0 + j) * Ec);
            float4 w1 = *(const float4*)(Wr + (d0 + j) * Ec + 4);
            acc[0] += xs[j] * w0.x; acc[1] += xs[j] * w0.y;
            acc[2] += xs[j] * w0.z; acc[3] += xs[j] * w0.w;
            acc[4] += xs[j] * w1.x; acc[5] += xs[j] * w1.y;
            acc[6] += xs[j] * w1.z; acc[7] += xs[j] * w1.w;
        }
    }
#pragma unroll
    for (int e = 0; e < Ec; e++)
#pragma unroll
        for (int o = 16; o > 0; o >>= 1)
            acc[e] += __shfl_xor_sync(0xffffffffu, acc[e], o);
    if (lane == 0) {
        float mx = acc[0];
#pragma unroll
        for (int e = 1; e < Ec; e++) mx = fmaxf(mx, acc[e]);
        float p[Ec], s = 0.0f;
#pragma unroll
        for (int e = 0; e < Ec; e++) { p[e] = __expf(acc[e] - mx); s += p[e]; }
        float inv = 1.0f / s;
        int i1 = 0;
#pragma unroll
        for (int e = 1; e < Ec; e++) if (p[e] > p[i1]) i1 = e;
        int i2 = (i1 == 0) ? 1 : 0;
#pragma unroll
        for (int e = 0; e < Ec; e++) if (e != i1 && p[e] > p[i2]) i2 = e;
        g_topi[2 * n] = i1;     g_topv[2 * n] = p[i1] * inv;
        g_topi[2 * n + 1] = i2; g_topv[2 * n + 1] = p[i2] * inv;
        atomicAdd(&g_cnt[i1], 1);
        atomicAdd(&g_cnt[i2], 1);
    }
}

// ---------------- launch 3: fused scan + scatter ----------------
__global__ void k_scansc() {
    __shared__ int soff[Ec];
    if (threadIdx.x == 0) {
        int o = 0;
#pragma unroll
        for (int e = 0; e < Ec; e++) {
            soff[e] = o;
            o += ((g_cnt[e] + TMp - 1) / TMp) * TMp;
        }
        if (blockIdx.x == 0) {
#pragma unroll
            for (int e = 0; e < Ec; e++) g_off[e] = soff[e];
            g_off[Ec] = o;
        }
    }
    __syncthreads();
    int n = blockIdx.x * blockDim.x + threadIdx.x;
    if (n >= NT) return;
#pragma unroll
    for (int k = 0; k < 2; k++) {
        int e = g_topi[2 * n + k];
        int pos = soff[e] + atomicAdd(&g_cur[e], 1);
        g_tok[pos] = n;
        g_gate[pos] = g_topv[2 * n + k];
    }
}

// ============ launch 4: FFN1  h = silu(X@W1) * (X@W3), CTA 128x64, 2 CTA/SM ============
__global__ void __launch_bounds__(256, 2) k_ffn1() {
    extern __shared__ __half sm[];
    int m0 = blockIdx.y * 128;
    if (m0 >= g_off[Ec]) return;
    int e = 0;
#pragma unroll
    for (int i = 1; i < Ec; i++) if (m0 >= g_off[i]) e = i;
    int n0 = blockIdx.x * 64;

    int tid = threadIdx.x, wid = tid >> 5, lane = tid & 31;
    int wm = wid & 3, wn = wid >> 2;              // warp tile 32 x 32 (dual GEMM)
    int gi = lane >> 2, ti = lane & 3;
    uint32_t smb = smem_u32(sm);

    int rA = tid >> 1, chA = (tid & 1) * 32;      // A: 128 rows x 64 halves
    int rB = tid >> 2, cnB = (tid & 3) * 16;      // B: 64 rows x 64 halves
    int tok = g_tok[m0 + rA];
    const __half* srcA  = g_xh + (size_t)(tok < 0 ? 0 : tok) * Dc + chA;
    const __half* srcB1 = g_w1h + ((size_t)e * Dc + rB) * HP2 + n0 + cnB;
    const __half* srcB3 = g_w3h + ((size_t)e * Dc + rB) * HP2 + n0 + cnB;
    uint32_t dstA  = smb + (uint32_t)(rA * SA1 + chA) * 2;
    uint32_t dstB1 = smb + (uint32_t)(F1_B1OFF + rB * SBF1 + cnB) * 2;
    uint32_t dstB3 = smb + (uint32_t)(F1_B3OFF + rB * SBF1 + cnB) * 2;
    const uint32_t STGB = (uint32_t)F1_STGH * 2;

    auto issue = [&](int kc, int buf) {
        int k0 = kc * KCH;
        uint32_t so = buf * STGB;
        const __half* sA = srcA + k0;
        uint32_t dA = dstA + so;
        CP16(dA, sA); CP16(dA + 16, sA + 8); CP16(dA + 32, sA + 16); CP16(dA + 48, sA + 24);
        const __half* s1 = srcB1 + (size_t)k0 * HP2;
        uint32_t d1 = dstB1 + so;
        CP16(d1, s1); CP16(d1 + 16, s1 + 8);
        const __half* s3 = srcB3 + (size_t)k0 * HP2;
        uint32_t d3 = dstB3 + so;
        CP16(d3, s3); CP16(d3 + 16, s3 + 8);
    };

    int aRow = wm * 32 + (lane & 7) + 8 * ((lane >> 3) & 1);
    uint32_t aBase = smb + (uint32_t)(aRow * SA1 + 8 * (lane >> 4)) * 2;
    int bRowK = (lane & 7) + 8 * ((lane >> 3) & 1);
    uint32_t bBase = smb + (uint32_t)(F1_B1OFF + bRowK * SBF1 + wn * 32 + (lane >> 4) * 8) * 2;
    const uint32_t B3D = (uint32_t)(F1_B3OFF - F1_B1OFF) * 2;   // 9216

    float acc1[2][4][4], acc3[2][4][4];
#pragma unroll
    for (int mt = 0; mt < 2; mt++)
#pragma unroll
        for (int nt = 0; nt < 4; nt++)
#pragma unroll
            for (int j = 0; j < 4; j++) { acc1[mt][nt][j] = 0.f; acc3[mt][nt][j] = 0.f; }

    const int nc = Dc / KCH;   // 16
    issue(0, 0); CP_COMMIT();
    issue(1, 1); CP_COMMIT();

    for (int c = 0; c < nc; ++c) {
        if (c + 1 < nc) CP_WAIT1(); else CP_WAIT0();
        __syncthreads();
        if (c + 2 < nc) { issue(c + 2, (c + 2) % 3); CP_COMMIT(); }
        uint32_t so = (uint32_t)(c % 3) * STGB;
        uint32_t aA = aBase + so;
        uint32_t bB = bBase + so;
#pragma unroll
        for (int ks = 0; ks < 4; ks++) {
            uint32_t af[2][4];
            ldsm_x4(af[0], aA + ks * 32);
            ldsm_x4(af[1], aA + 2304 + ks * 32);        // +16 rows * 144B
#pragma unroll
            for (int np = 0; np < 2; np++) {            // nt pairs
                uint32_t bo = bB + ks * 2304 + np * 32; // +16 k-rows * 144B ; +16 cols
                uint32_t bf1[4], bf3[4];
                ldsm_x4t(bf1, bo);
                ldsm_x4t(bf3, bo + B3D);
                mma16(acc1[0][2 * np],     af[0], bf1);
                mma16(acc1[1][2 * np],     af[1], bf1);
                mma16(acc1[0][2 * np + 1], af[0], bf1 + 2);
                mma16(acc1[1][2 * np + 1], af[1], bf1 + 2);
                mma16(acc3[0][2 * np],     af[0], bf3);
                mma16(acc3[1][2 * np],     af[1], bf3);
                mma16(acc3[0][2 * np + 1], af[0], bf3 + 2);
                mma16(acc3[1][2 * np + 1], af[1], bf3 + 2);
            }
        }
    }

    // epilogue: silu(d1)*d3 -> g_h (fp16)
#pragma unroll
    for (int mt = 0; mt < 2; mt++) {
#pragma unroll
        for (int nt = 0; nt < 4; nt++) {
            int row = m0 + wm * 32 + mt * 16 + gi;
            int col = n0 + wn * 32 + nt * 8 + 2 * ti;
            const float* d1 = acc1[mt][nt];
            const float* d3 = acc3[mt][nt];
            float h0 = d1[0] / (1.0f + __expf(-d1[0])) * d3[0];
            float h1 = d1[1] / (1.0f + __expf(-d1[1])) * d3[1];
            float h2 = d1[2] / (1.0f + __expf(-d1[2])) * d3[2];
            float h3 = d1[3] / (1.0f + __expf(-d1[3])) * d3[3];
            *(__half2*)(g_h + (size_t)row * HP2 + col)       = __floats2half2_rn(h0, h1);
            *(__half2*)(g_h + (size_t)(row + 8) * HP2 + col) = __floats2half2_rn(h2, h3);
        }
    }
}

// ============ launch 5: FFN2  out += gate * (h @ W2), CTA 128x128, 2 CTA/SM ============
__global__ void __launch_bounds__(256, 2) k_ffn2(float* __restrict__ out) {
    extern __shared__ __half sm[];
    int m0 = blockIdx.y * 128;
    if (m0 >= g_off[Ec]) return;
    int e = 0;
#pragma unroll
    for (int i = 1; i < Ec; i++) if (m0 >= g_off[i]) e = i;
    int n0 = blockIdx.x * 128;

    int tid = threadIdx.x, wid = tid >> 5, lane = tid & 31;
    int wm = wid & 3, wn = wid >> 2;              // warp tile 32 x 64
    int gi = lane >> 2, ti = lane & 3;
    uint32_t smb = smem_u32(sm);

    int rA = tid >> 1, chA = (tid & 1) * 32;
    int rB = tid >> 2, cnB = (tid & 3) * 32;
    const __half* srcA = g_h + (size_t)(m0 + rA) * HP2 + chA;
    const __half* srcB = g_w2h + ((size_t)e * HP2 + rB) * Dc + n0 + cnB;
    uint32_t dstA = smb + (uint32_t)(rA * SA1 + chA) * 2;
    uint32_t dstB = smb + (uint32_t)(F2_BOFF + rB * SBF2 + cnB) * 2;
    const uint32_t STGB = (uint32_t)F2_STGH * 2;

    auto issue = [&](int kc, int buf) {
        int k0 = kc * KCH;
        uint32_t so = buf * STGB;
        const __half* sA = srcA + k0;
        uint32_t dA = dstA + so;
        CP16(dA, sA); CP16(dA + 16, sA + 8); CP16(dA + 32, sA + 16); CP16(dA + 48, sA + 24);
        const __half* sB = srcB + (size_t)k0 * Dc;
        uint32_t dB = dstB + so;
        CP16(dB, sB); CP16(dB + 16, sB + 8); CP16(dB + 32, sB + 16); CP16(dB + 48, sB + 24);
    };

    int aRow = wm * 32 + (lane & 7) + 8 * ((lane >> 3) & 1);
    uint32_t aBase = smb + (uint32_t)(aRow * SA1 + 8 * (lane >> 4)) * 2;
    int bRowK = (lane & 7) + 8 * ((lane >> 3) & 1);
    uint32_t bBase = smb + (uint32_t)(F2_BOFF + bRowK * SBF2 + wn * 64 + (lane >> 4) * 8) * 2;

    float acc[2][8][4];
#pragma unroll
    for (int mt = 0; mt < 2; mt++)
#pragma unroll
        for (int nt = 0; nt < 8; nt++)
#pragma unroll
            for (int j = 0; j < 4; j++) acc[mt][nt][j] = 0.f;

    const int nc = HP2 / KCH;   // 44
    issue(0, 0); CP_COMMIT();
    issue(1, 1); CP_COMMIT();

    for (int c = 0; c < nc; ++c) {
        if (c + 1 < nc) CP_WAIT1(); else CP_WAIT0();
        __syncthreads();
        if (c + 2 < nc) { issue(c + 2, (c + 2) % 3); CP_COMMIT(); }
        uint32_t so = (uint32_t)(c % 3) * STGB;
        uint32_t aA = aBase + so;
        uint32_t bB = bBase + so;
#pragma unroll
        for (int ks = 0; ks < 4; ks++) {
            uint32_t af[2][4];
            ldsm_x4(af[0], aA + ks * 32);
            ldsm_x4(af[1], aA + 2304 + ks * 32);
#pragma unroll
            for (int np = 0; np < 4; np++) {
                uint32_t bf[4];
                ldsm_x4t(bf, bB + ks * 4352 + np * 32);  // +16 k-rows * 272B ; +16 cols
                mma16(acc[0][2 * np],     af[0], bf);
                mma16(acc[1][2 * np],     af[1], bf);
                mma16(acc[0][2 * np + 1], af[0], bf + 2);
                mma16(acc[1][2 * np + 1], af[1], bf + 2);
            }
        }
    }

    // epilogue: fused combine -> atomicAdd into out[token]
#pragma unroll
    for (int mt = 0; mt < 2; mt++) {
        int row = m0 + wm * 32 + mt * 16 + gi;
        int tok0 = g_tok[row];
        int tok1 = g_tok[row + 8];
        float ga = g_gate[row];
        float gb = g_gate[row + 8];
        float* o0 = out + (size_t)(tok0 < 0 ? 0 : tok0) * Dc;
        float* o1 = out + (size_t)(tok1 < 0 ? 0 : tok1) * Dc;
#pragma unroll
        for (int nt = 0; nt < 8; nt++) {
            int col = n0 + wn * 64 + nt * 8 + 2 * ti;
            const float* d = acc[mt][nt];
            if (tok0 >= 0) {
                atomicAdd(o0 + col,     ga * d[0]);
                atomicAdd(o0 + col + 1, ga * d[1]);
            }
            if (tok1 >= 0) {
                atomicAdd(o1 + col,     gb * d[2]);
                atomicAdd(o1 + col + 1, gb * d[3]);
            }
        }
    }
}

// ---------------- launch ----------------
extern "C" void kernel_launch(void* const* d_in, const int* in_sizes, int n_in,
                              void* d_out, int out_size) {
    const float* x  = (const float*)d_in[0];
    const float* Wr = (const float*)d_in[1];
    const float* W1 = (const float*)d_in[2];
    const float* W2 = (const float*)d_in[3];
    const float* W3 = (const float*)d_in[4];
    float* out = (float*)d_out;

    cudaFuncSetAttribute(k_ffn1, cudaFuncAttributeMaxDynamicSharedMemorySize, F1_SMEM);
    cudaFuncSetAttribute(k_ffn2, cudaFuncAttributeMaxDynamicSharedMemorySize, F2_SMEM);

    k_prep<<<PREP13 + PREPW2, 256>>>(W1, W3, W2, out);         // 1 (all converts + zero out)
    k_routerx<<<NT / 8, 256>>>(x, Wr);                         // 2
    k_scansc<<<NT / 256, 256>>>();                             // 3
    k_ffn1<<<dim3(HP2 / 64, MMAX / 128), 256, F1_SMEM>>>();    // 4  <- profiled
    k_ffn2<<<dim3(Dc / 128, MMAX / 128), 256, F2_SMEM>>>(out); // 5 (fused combine)
}

// round 13
// speedup vs baseline: 1.2573x; 1.0121x over previous
#include <cuda_runtime.h>
#include <cuda_fp16.h>
#include <cstdint>

// ---------------- problem constants ----------------
#define Dc   1024
#define Ec   8
#define Hc   2730
#define HP2  2816            // H padded to 22*128
#define NT   8192
#define TMp  128             // per-expert row padding
#define MMAX (2*NT + Ec*TMp) // 17408
#define KCH  64              // K halves per pipeline chunk (4 x k16)

// smem strides (halves)
#define SA1  72              // A row stride (64 K + 8 pad)  = 144 B
#define SBF1 72              // FFN1 B row stride (64 N + 8 pad)
#define SBF2 136             // FFN2 B row stride (128 N + 8 pad) = 272 B

// FFN1 stage (halves): A[128][72]=9216, B1[64][72]=4608, B3[64][72]=4608
#define F1_B1OFF 9216
#define F1_B3OFF 13824
#define F1_STGH  18432
#define F1_SMEM  (3 * F1_STGH * 2)    // 110592 B  (2 CTAs/SM)
// FFN2 stage: A[128][72]=9216, B[64][136]=8704
#define F2_BOFF  9216
#define F2_STGH  17920
#define F2_SMEM  (3 * F2_STGH * 2)    // 107520 B  (2 CTAs/SM)

// ---------------- device scratch ----------------
__device__ int    g_cnt[Ec];
__device__ int    g_cur[Ec];
__device__ int    g_off[Ec + 1];
__device__ int    g_tok[MMAX];
__device__ float  g_gate[MMAX];
__device__ int    g_topi[NT * 2];
__device__ float  g_topv[NT * 2];
__device__ __half g_w1h[(size_t)Ec * Dc * HP2];   // W1 fp16 [E][Dc][HP2]
__device__ __half g_w3h[(size_t)Ec * Dc * HP2];   // W3 fp16
__device__ __half g_w2h[(size_t)Ec * HP2 * Dc];   // W2 fp16 [E][HP2][Dc]
__device__ __half g_xh[(size_t)NT * Dc];          // x fp16
__device__ __half g_h[(size_t)MMAX * HP2];        // activations fp16

// ---------------- helpers ----------------
__device__ __forceinline__ uint32_t smem_u32(const void* p) {
    uint32_t a;
    asm("{ .reg .u64 t; cvta.to.shared.u64 t, %1; cvt.u32.u64 %0, t; }" : "=r"(a) : "l"(p));
    return a;
}
#define CP16(dst, src) asm volatile("cp.async.cg.shared.global [%0], [%1], 16;" :: "r"(dst), "l"(src) : "memory")
#define CP_COMMIT()    asm volatile("cp.async.commit_group;" ::: "memory")
#define CP_WAIT0()     asm volatile("cp.async.wait_group 0;" ::: "memory")
#define CP_WAIT1()     asm volatile("cp.async.wait_group 1;" ::: "memory")

__device__ __forceinline__ void ldsm_x4(uint32_t* r, uint32_t a) {
    asm volatile("ldmatrix.sync.aligned.m8n8.x4.shared.b16 {%0,%1,%2,%3}, [%4];"
        : "=r"(r[0]), "=r"(r[1]), "=r"(r[2]), "=r"(r[3]) : "r"(a));
}
__device__ __forceinline__ void ldsm_x4t(uint32_t* r, uint32_t a) {
    asm volatile("ldmatrix.sync.aligned.m8n8.x4.trans.shared.b16 {%0,%1,%2,%3}, [%4];"
        : "=r"(r[0]), "=r"(r[1]), "=r"(r[2]), "=r"(r[3]) : "r"(a));
}
__device__ __forceinline__ void mma16(float* d, const uint32_t* a, const uint32_t* b) {
    asm volatile(
        "mma.sync.aligned.m16n8k16.row.col.f32.f16.f16.f32 "
        "{%0,%1,%2,%3}, {%4,%5,%6,%7}, {%8,%9}, {%0,%1,%2,%3};"
        : "+f"(d[0]), "+f"(d[1]), "+f"(d[2]), "+f"(d[3])
        : "r"(a[0]), "r"(a[1]), "r"(a[2]), "r"(a[3]), "r"(b[0]), "r"(b[1]));
}

// ---------------- s1: bookkeeping init (must precede router atomics) ----------------
__global__ void k_init() {
    int i = blockIdx.x * blockDim.x + threadIdx.x;
    if (i < Ec) { g_cnt[i] = 0; g_cur[i] = 0; }
    if (i < MMAX) { g_tok[i] = -1; g_gate[i] = 0.0f; }
}

// ---------------- s0: convert W1,W3 to fp16 + zero out ----------------
__global__ void k_prep13(const float* __restrict__ W1, const float* __restrict__ W3,
                         float* __restrict__ out) {
    // zero out: 8192 blocks x 1024 floats
    {
        float4 z = make_float4(0.f, 0.f, 0.f, 0.f);
        *(float4*)(out + (size_t)blockIdx.x * 1024 + threadIdx.x * 4) = z;
    }

    int row = blockIdx.x;                       // 0 .. E*Dc-1
    const float* i1 = W1 + (size_t)row * Hc;
    const float* i3 = W3 + (size_t)row * Hc;
    __half* o1 = g_w1h + (size_t)row * HP2;
    __half* o3 = g_w3h + (size_t)row * HP2;
    for (int u = threadIdx.x; u < HP2 / 8; u += 256) {
        int j = u * 8;
        __half2 v1[4], v3[4];
        if (j + 8 <= Hc) {
            float2 a0 = *(const float2*)(i1 + j),     a1 = *(const float2*)(i1 + j + 2);
            float2 a2 = *(const float2*)(i1 + j + 4), a3 = *(const float2*)(i1 + j + 6);
            v1[0] = __floats2half2_rn(a0.x, a0.y); v1[1] = __floats2half2_rn(a1.x, a1.y);
            v1[2] = __floats2half2_rn(a2.x, a2.y); v1[3] = __floats2half2_rn(a3.x, a3.y);
            float2 b0 = *(const float2*)(i3 + j),     b1 = *(const float2*)(i3 + j + 2);
            float2 b2 = *(const float2*)(i3 + j + 4), b3 = *(const float2*)(i3 + j + 6);
            v3[0] = __floats2half2_rn(b0.x, b0.y); v3[1] = __floats2half2_rn(b1.x, b1.y);
            v3[2] = __floats2half2_rn(b2.x, b2.y); v3[3] = __floats2half2_rn(b3.x, b3.y);
        } else {
#pragma unroll
            for (int t = 0; t < 4; t++) {
                int c0 = j + 2 * t, c1 = j + 2 * t + 1;
                float f0 = (c0 < Hc) ? i1[c0] : 0.f;
                float f1 = (c1 < Hc) ? i1[c1] : 0.f;
                v1[t] = __floats2half2_rn(f0, f1);
                float g0 = (c0 < Hc) ? i3[c0] : 0.f;
                float g1 = (c1 < Hc) ? i3[c1] : 0.f;
                v3[t] = __floats2half2_rn(g0, g1);
            }
        }
        *(uint4*)(o1 + j) = *(uint4*)v1;
        *(uint4*)(o3 + j) = *(uint4*)v3;
    }
}

// ---------------- s1: convert W2 to fp16 (row-padded), overlaps FFN1 ----------------
__global__ void k_w2h(const float* __restrict__ in) {
    int row = blockIdx.x;                       // 0 .. E*HP2-1
    int e = row / HP2, hp = row % HP2;
    __half* op = g_w2h + (size_t)row * Dc;
    int j = threadIdx.x * 8;                    // 128 threads * 8 = 1024
    __half2 v[4];
    if (hp < Hc) {
        const float* ip = in + ((size_t)e * Hc + hp) * Dc + j;
        float4 a = *(const float4*)ip, b = *(const float4*)(ip + 4);
        v[0] = __floats2half2_rn(a.x, a.y); v[1] = __floats2half2_rn(a.z, a.w);
        v[2] = __floats2half2_rn(b.x, b.y); v[3] = __floats2half2_rn(b.z, b.w);
    } else {
        v[0] = v[1] = v[2] = v[3] = __floats2half2_rn(0.f, 0.f);
    }
    *(uint4*)(op + j) = *(uint4*)v;
}

// ---------------- s1: router (+ x -> fp16) ----------------
__global__ void k_routerx(const float* __restrict__ x, const float* __restrict__ Wr) {
    int warp = threadIdx.x >> 5, lane = threadIdx.x & 31;
    int n = blockIdx.x * 8 + warp;
    if (n >= NT) return;
    const float* xr = x + (size_t)n * Dc;
    __half* xo = g_xh + (size_t)n * Dc;
    float acc[Ec];
#pragma unroll
    for (int e = 0; e < Ec; e++) acc[e] = 0.0f;
    for (int d0 = lane * 4; d0 < Dc; d0 += 128) {
        float4 xv = *(const float4*)(xr + d0);
        __half2 h01 = __floats2half2_rn(xv.x, xv.y);
        __half2 h23 = __floats2half2_rn(xv.z, xv.w);
        uint2 pk;
        pk.x = *(uint32_t*)&h01; pk.y = *(uint32_t*)&h23;
        *(uint2*)(xo + d0) = pk;
        float xs[4] = {xv.x, xv.y, xv.z, xv.w};
#pragma unroll
        for (int j = 0; j < 4; j++) {
            float4 w0 = *(const float4*)(Wr + (d0 + j) * Ec);
            float4 w1 = *(const float4*)(Wr + (d0 + j) * Ec + 4);
            acc[0] += xs[j] * w0.x; acc[1] += xs[j] * w0.y;
            acc[2] += xs[j] * w0.z; acc[3] += xs[j] * w0.w;
            acc[4] += xs[j] * w1.x; acc[5] += xs[j] * w1.y;
            acc[6] += xs[j] * w1.z; acc[7] += xs[j] * w1.w;
        }
    }
#pragma unroll
    for (int e = 0; e < Ec; e++)
#pragma unroll
        for (int o = 16; o > 0; o >>= 1)
            acc[e] += __shfl_xor_sync(0xffffffffu, acc[e], o);
    if (lane == 0) {
        float mx = acc[0];
#pragma unroll
        for (int e = 1; e < Ec; e++) mx = fmaxf(mx, acc[e]);
        float p[Ec], s = 0.0f;
#pragma unroll
        for (int e = 0; e < Ec; e++) { p[e] = __expf(acc[e] - mx); s += p[e]; }
        float inv = 1.0f / s;
        int i1 = 0;
#pragma unroll
        for (int e = 1; e < Ec; e++) if (p[e] > p[i1]) i1 = e;
        int i2 = (i1 == 0) ? 1 : 0;
#pragma unroll
        for (int e = 0; e < Ec; e++) if (e != i1 && p[e] > p[i2]) i2 = e;
        g_topi[2 * n] = i1;     g_topv[2 * n] = p[i1] * inv;
        g_topi[2 * n + 1] = i2; g_topv[2 * n + 1] = p[i2] * inv;
        atomicAdd(&g_cnt[i1], 1);
        atomicAdd(&g_cnt[i2], 1);
    }
}

// ---------------- s1: fused scan + scatter ----------------
__global__ void k_scansc() {
    __shared__ int soff[Ec];
    if (threadIdx.x == 0) {
        int o = 0;
#pragma unroll
        for (int e = 0; e < Ec; e++) {
            soff[e] = o;
            o += ((g_cnt[e] + TMp - 1) / TMp) * TMp;
        }
        if (blockIdx.x == 0) {
#pragma unroll
            for (int e = 0; e < Ec; e++) g_off[e] = soff[e];
            g_off[Ec] = o;
        }
    }
    __syncthreads();
    int n = blockIdx.x * blockDim.x + threadIdx.x;
    if (n >= NT) return;
#pragma unroll
    for (int k = 0; k < 2; k++) {
        int e = g_topi[2 * n + k];
        int pos = soff[e] + atomicAdd(&g_cur[e], 1);
        g_tok[pos] = n;
        g_gate[pos] = g_topv[2 * n + k];
    }
}

// ============ s0: FFN1  h = silu(X@W1) * (X@W3), CTA 128x64, 2 CTA/SM ============
__global__ void __launch_bounds__(256, 2) k_ffn1() {
    extern __shared__ __half sm[];
    int m0 = blockIdx.y * 128;
    if (m0 >= g_off[Ec]) return;
    int e = 0;
#pragma unroll
    for (int i = 1; i < Ec; i++) if (m0 >= g_off[i]) e = i;
    int n0 = blockIdx.x * 64;

    int tid = threadIdx.x, wid = tid >> 5, lane = tid & 31;
    int wm = wid & 3, wn = wid >> 2;              // warp tile 32 x 32 (dual GEMM)
    int gi = lane >> 2, ti = lane & 3;
    uint32_t smb = smem_u32(sm);

    int rA = tid >> 1, chA = (tid & 1) * 32;      // A: 128 rows x 64 halves
    int rB = tid >> 2, cnB = (tid & 3) * 16;      // B: 64 rows x 64 halves
    int tok = g_tok[m0 + rA];
    const __half* srcA  = g_xh + (size_t)(tok < 0 ? 0 : tok) * Dc + chA;
    const __half* srcB1 = g_w1h + ((size_t)e * Dc + rB) * HP2 + n0 + cnB;
    const __half* srcB3 = g_w3h + ((size_t)e * Dc + rB) * HP2 + n0 + cnB;
    uint32_t dstA  = smb + (uint32_t)(rA * SA1 + chA) * 2;
    uint32_t dstB1 = smb + (uint32_t)(F1_B1OFF + rB * SBF1 + cnB) * 2;
    uint32_t dstB3 = smb + (uint32_t)(F1_B3OFF + rB * SBF1 + cnB) * 2;
    const uint32_t STGB = (uint32_t)F1_STGH * 2;

    auto issue = [&](int kc, int buf) {
        int k0 = kc * KCH;
        uint32_t so = buf * STGB;
        const __half* sA = srcA + k0;
        uint32_t dA = dstA + so;
        CP16(dA, sA); CP16(dA + 16, sA + 8); CP16(dA + 32, sA + 16); CP16(dA + 48, sA + 24);
        const __half* s1 = srcB1 + (size_t)k0 * HP2;
        uint32_t d1 = dstB1 + so;
        CP16(d1, s1); CP16(d1 + 16, s1 + 8);
        const __half* s3 = srcB3 + (size_t)k0 * HP2;
        uint32_t d3 = dstB3 + so;
        CP16(d3, s3); CP16(d3 + 16, s3 + 8);
    };

    int aRow = wm * 32 + (lane & 7) + 8 * ((lane >> 3) & 1);
    uint32_t aBase = smb + (uint32_t)(aRow * SA1 + 8 * (lane >> 4)) * 2;
    int bRowK = (lane & 7) + 8 * ((lane >> 3) & 1);
    uint32_t bBase = smb + (uint32_t)(F1_B1OFF + bRowK * SBF1 + wn * 32 + (lane >> 4) * 8) * 2;
    const uint32_t B3D = (uint32_t)(F1_B3OFF - F1_B1OFF) * 2;   // 9216

    float acc1[2][4][4], acc3[2][4][4];
#pragma unroll
    for (int mt = 0; mt < 2; mt++)
#pragma unroll
        for (int nt = 0; nt < 4; nt++)
#pragma unroll
            for (int j = 0; j < 4; j++) { acc1[mt][nt][j] = 0.f; acc3[mt][nt][j] = 0.f; }

    const int nc = Dc / KCH;   // 16
    issue(0, 0); CP_COMMIT();
    issue(1, 1); CP_COMMIT();

    for (int c = 0; c < nc; ++c) {
        if (c + 1 < nc) CP_WAIT1(); else CP_WAIT0();
        __syncthreads();
        if (c + 2 < nc) { issue(c + 2, (c + 2) % 3); CP_COMMIT(); }
        uint32_t so = (uint32_t)(c % 3) * STGB;
        uint32_t aA = aBase + so;
        uint32_t bB = bBase + so;
#pragma unroll
        for (int ks = 0; ks < 4; ks++) {
            uint32_t af[2][4];
            ldsm_x4(af[0], aA + ks * 32);
            ldsm_x4(af[1], aA + 2304 + ks * 32);        // +16 rows * 144B
#pragma unroll
            for (int np = 0; np < 2; np++) {            // nt pairs
                uint32_t bo = bB + ks * 2304 + np * 32; // +16 k-rows * 144B ; +16 cols
                uint32_t bf1[4], bf3[4];
                ldsm_x4t(bf1, bo);
                ldsm_x4t(bf3, bo + B3D);
                mma16(acc1[0][2 * np],     af[0], bf1);
                mma16(acc1[1][2 * np],     af[1], bf1);
                mma16(acc1[0][2 * np + 1], af[0], bf1 + 2);
                mma16(acc1[1][2 * np + 1], af[1], bf1 + 2);
                mma16(acc3[0][2 * np],     af[0], bf3);
                mma16(acc3[1][2 * np],     af[1], bf3);
                mma16(acc3[0][2 * np + 1], af[0], bf3 + 2);
                mma16(acc3[1][2 * np + 1], af[1], bf3 + 2);
            }
        }
    }

    // epilogue: silu(d1)*d3 -> g_h (fp16)
#pragma unroll
    for (int mt = 0; mt < 2; mt++) {
#pragma unroll
        for (int nt = 0; nt < 4; nt++) {
            int row = m0 + wm * 32 + mt * 16 + gi;
            int col = n0 + wn * 32 + nt * 8 + 2 * ti;
            const float* d1 = acc1[mt][nt];
            const float* d3 = acc3[mt][nt];
            float h0 = d1[0] / (1.0f + __expf(-d1[0])) * d3[0];
            float h1 = d1[1] / (1.0f + __expf(-d1[1])) * d3[1];
            float h2 = d1[2] / (1.0f + __expf(-d1[2])) * d3[2];
            float h3 = d1[3] / (1.0f + __expf(-d1[3])) * d3[3];
            *(__half2*)(g_h + (size_t)row * HP2 + col)       = __floats2half2_rn(h0, h1);
            *(__half2*)(g_h + (size_t)(row + 8) * HP2 + col) = __floats2half2_rn(h2, h3);
        }
    }
}

// ============ s0: FFN2  out += gate * (h @ W2), CTA 128x128, 2 CTA/SM ============
__global__ void __launch_bounds__(256, 2) k_ffn2(float* __restrict__ out) {
    extern __shared__ __half sm[];
    int m0 = blockIdx.y * 128;
    if (m0 >= g_off[Ec]) return;
    int e = 0;
#pragma unroll
    for (int i = 1; i < Ec; i++) if (m0 >= g_off[i]) e = i;
    int n0 = blockIdx.x * 128;

    int tid = threadIdx.x, wid = tid >> 5, lane = tid & 31;
    int wm = wid & 3, wn = wid >> 2;              // warp tile 32 x 64
    int gi = lane >> 2, ti = lane & 3;
    uint32_t smb = smem_u32(sm);

    int rA = tid >> 1, chA = (tid & 1) * 32;
    int rB = tid >> 2, cnB = (tid & 3) * 32;
    const __half* srcA = g_h + (size_t)(m0 + rA) * HP2 + chA;
    const __half* srcB = g_w2h + ((size_t)e * HP2 + rB) * Dc + n0 + cnB;
    uint32_t dstA = smb + (uint32_t)(rA * SA1 + chA) * 2;
    uint32_t dstB = smb + (uint32_t)(F2_BOFF + rB * SBF2 + cnB) * 2;
    const uint32_t STGB = (uint32_t)F2_STGH * 2;

    auto issue = [&](int kc, int buf) {
        int k0 = kc * KCH;
        uint32_t so = buf * STGB;
        const __half* sA = srcA + k0;
        uint32_t dA = dstA + so;
        CP16(dA, sA); CP16(dA + 16, sA + 8); CP16(dA + 32, sA + 16); CP16(dA + 48, sA + 24);
        const __half* sB = srcB + (size_t)k0 * Dc;
        uint32_t dB = dstB + so;
        CP16(dB, sB); CP16(dB + 16, sB + 8); CP16(dB + 32, sB + 16); CP16(dB + 48, sB + 24);
    };

    int aRow = wm * 32 + (lane & 7) + 8 * ((lane >> 3) & 1);
    uint32_t aBase = smb + (uint32_t)(aRow * SA1 + 8 * (lane >> 4)) * 2;
    int bRowK = (lane & 7) + 8 * ((lane >> 3) & 1);
    uint32_t bBase = smb + (uint32_t)(F2_BOFF + bRowK * SBF2 + wn * 64 + (lane >> 4) * 8) * 2;

    float acc[2][8][4];
#pragma unroll
    for (int mt = 0; mt < 2; mt++)
#pragma unroll
        for (int nt = 0; nt < 8; nt++)
#pragma unroll
            for (int j = 0; j < 4; j++) acc[mt][nt][j] = 0.f;

    const int nc = HP2 / KCH;   // 44
    issue(0, 0); CP_COMMIT();
    issue(1, 1); CP_COMMIT();

    for (int c = 0; c < nc; ++c) {
        if (c + 1 < nc) CP_WAIT1(); else CP_WAIT0();
        __syncthreads();
        if (c + 2 < nc) { issue(c + 2, (c + 2) % 3); CP_COMMIT(); }
        uint32_t so = (uint32_t)(c % 3) * STGB;
        uint32_t aA = aBase + so;
        uint32_t bB = bBase + so;
#pragma unroll
        for (int ks = 0; ks < 4; ks++) {
            uint32_t af[2][4];
            ldsm_x4(af[0], aA + ks * 32);
            ldsm_x4(af[1], aA + 2304 + ks * 32);
#pragma unroll
            for (int np = 0; np < 4; np++) {
                uint32_t bf[4];
                ldsm_x4t(bf, bB + ks * 4352 + np * 32);  // +16 k-rows * 272B ; +16 cols
                mma16(acc[0][2 * np],     af[0], bf);
                mma16(acc[1][2 * np],     af[1], bf);
                mma16(acc[0][2 * np + 1], af[0], bf + 2);
                mma16(acc[1][2 * np + 1], af[1], bf + 2);
            }
        }
    }

    // epilogue: fused combine -> atomicAdd into out[token]
#pragma unroll
    for (int mt = 0; mt < 2; mt++) {
        int row = m0 + wm * 32 + mt * 16 + gi;
        int tok0 = g_tok[row];
        int tok1 = g_tok[row + 8];
        float ga = g_gate[row];
        float gb = g_gate[row + 8];
        float* o0 = out + (size_t)(tok0 < 0 ? 0 : tok0) * Dc;
        float* o1 = out + (size_t)(tok1 < 0 ? 0 : tok1) * Dc;
#pragma unroll
        for (int nt = 0; nt < 8; nt++) {
            int col = n0 + wn * 64 + nt * 8 + 2 * ti;
            const float* d = acc[mt][nt];
            if (tok0 >= 0) {
                atomicAdd(o0 + col,     ga * d[0]);
                atomicAdd(o0 + col + 1, ga * d[1]);
            }
            if (tok1 >= 0) {
                atomicAdd(o1 + col,     gb * d[2]);
                atomicAdd(o1 + col + 1, gb * d[3]);
            }
        }
    }
}

// ---------------- launch: two-stream fork/join (graph-capture-legal) ----------------
extern "C" void kernel_launch(void* const* d_in, const int* in_sizes, int n_in,
                              void* d_out, int out_size) {
    const float* x  = (const float*)d_in[0];
    const float* Wr = (const float*)d_in[1];
    const float* W1 = (const float*)d_in[2];
    const float* W2 = (const float*)d_in[3];
    const float* W3 = (const float*)d_in[4];
    float* out = (float*)d_out;

    // one-time host-side resources (no device memory)
    static cudaStream_t s1 = nullptr;
    static cudaEvent_t e0 = nullptr, e1 = nullptr, e2 = nullptr;
    if (s1 == nullptr) {
        cudaStreamCreateWithFlags(&s1, cudaStreamNonBlocking);
        cudaEventCreateWithFlags(&e0, cudaEventDisableTiming);
        cudaEventCreateWithFlags(&e1, cudaEventDisableTiming);
        cudaEventCreateWithFlags(&e2, cudaEventDisableTiming);
        cudaFuncSetAttribute(k_ffn1, cudaFuncAttributeMaxDynamicSharedMemorySize, F1_SMEM);
        cudaFuncSetAttribute(k_ffn2, cudaFuncAttributeMaxDynamicSharedMemorySize, F2_SMEM);
    }

    // fork: s1 branch = init -> router -> scansc -> (e1) -> w2h -> (e2)
    cudaEventRecord(e0, 0);
    cudaStreamWaitEvent(s1, e0, 0);
    k_init<<<(MMAX + 255) / 256, 256, 0, s1>>>();
    k_routerx<<<NT / 8, 256, 0, s1>>>(x, Wr);
    k_scansc<<<NT / 256, 256, 0, s1>>>();
    cudaEventRecord(e1, s1);
    k_w2h<<<Ec * HP2, 128, 0, s1>>>(W2);
    cudaEventRecord(e2, s1);

    // s0 (default) branch = prep13 ; join e1 ; ffn1 ; join e2 ; ffn2
    k_prep13<<<Ec * Dc, 256>>>(W1, W3, out);
    cudaStreamWaitEvent(0, e1, 0);
    k_ffn1<<<dim3(HP2 / 64, MMAX / 128), 256, F1_SMEM>>>();
    cudaStreamWaitEvent(0, e2, 0);
    k_ffn2<<<dim3(Dc / 128, MMAX / 128), 256, F2_SMEM>>>(out);
}